// round 12
// baseline (speedup 1.0000x reference)
#include <cuda_runtime.h>
#include <cuda_bf16.h>
#include <cstdint>
#include <math.h>

#define N_STM 65536
#define N_LTM 65536
#define TOP_M 2048
#define NBIN  4096
#define TVOL  (5*96*96*96)
#define NSMAX 516

// ---------------- scratch (static zero-init; replay-safe) -------------------
__device__ int                g_hist[NBIN];
__device__ int                g_scal[8];   // 4:n_act 5:n_stages
__device__ int                g_sel[TOP_M];
__device__ int                g_boundary[N_STM];
__device__ float              g_Kproj[TOP_M*64];
__device__ float              g_kpN[TOP_M*64];
__device__ __align__(16) __nv_bfloat16 g_kpB[TOP_M*64];
__device__ float              g_omega[TOP_M];
__device__ float              g_lknC[(size_t)(N_LTM+128)*64];
__device__ __align__(16) __nv_bfloat16 g_lknB[(size_t)(N_LTM+128)*64];
__device__ unsigned           g_ajinv[N_LTM+128];
__device__ float              g_smax[(size_t)TOP_M*NSMAX];
__device__ unsigned           g_gmaxU[TOP_M];
__device__ unsigned long long g_best[TOP_M];
__device__ unsigned long long g_key[TOP_M];
__device__ int                g_unm[TOP_M];
__device__ int                g_free[TOP_M];

// ---------------- helpers ---------------------------------------------------
__device__ __forceinline__ unsigned fmono(float f) {
    unsigned u = __float_as_uint(f);
    return (u & 0x80000000u) ? ~u : (u | 0x80000000u);
}
__device__ __forceinline__ float funmono(unsigned m) {
    unsigned u = (m & 0x80000000u) ? (m ^ 0x80000000u) : ~m;
    return __uint_as_float(u);
}
__device__ __forceinline__ unsigned long long stm_key(int i, float h) {
    return ((unsigned long long)__float_as_uint(h) << 32) | (0xFFFFFFFFu - (unsigned)i);
}
__device__ __forceinline__ int hbin(float h) {
    return min(max((int)(h * (float)NBIN), 0), NBIN - 1);
}
__device__ __forceinline__ void gw(float* w, float& inv) {
    w[0] = 1.0f; float sum = 1.0f;
    #pragma unroll
    for (int i = 1; i < 7; ++i) {
        w[i] = expf(-0.5f * (float)(i * i) / 4.0f);
        sum += 2.0f * w[i];
    }
    inv = 1.0f / sum;
}
__device__ __forceinline__ void mma16816(float* c, const unsigned* a, const unsigned* b) {
    asm volatile("mma.sync.aligned.m16n8k16.row.col.f32.bf16.bf16.f32 "
                 "{%0,%1,%2,%3}, {%4,%5,%6,%7}, {%8,%9}, {%0,%1,%2,%3};"
                 : "+f"(c[0]), "+f"(c[1]), "+f"(c[2]), "+f"(c[3])
                 : "r"(a[0]), "r"(a[1]), "r"(a[2]), "r"(a[3]), "r"(b[0]), "r"(b[1]));
}
// k-pair permutation: orig u32 col off (0..7 within 8-col chunk) -> pos so that
// (x, x+4) become adjacent (2x, 2x+1): pos = (off&3)*2 + (off>>2)
__device__ __forceinline__ int kperm(int cu) {
    return (cu & ~7) + ((cu & 3) * 2 + ((cu >> 2) & 1));
}

// ---- side: base-state copy (ltm->out head) + stm_V norm clip ---------------
__global__ void k_side(const float4* __restrict__ K, const float4* __restrict__ V,
                       const float4* __restrict__ e, const float4* __restrict__ h,
                       float4* __restrict__ out,
                       const float* __restrict__ stm_V, float* __restrict__ oSV) {
    if (blockIdx.x < 12608) {
        int i = blockIdx.x * blockDim.x + threadIdx.x;   // 3227648 total
        float4 v;
        if (i < 1048576)       v = K[i];
        else if (i < 3145728)  v = V[i - 1048576];
        else if (i < 3211264)  v = e[i - 3145728];
        else                   v = h[i - 3211264];
        out[i] = v;
    } else {
        int b = blockIdx.x - 12608;                      // 8192 blocks
        int w = threadIdx.x >> 5, lane = threadIdx.x & 31;
        size_t row = (size_t)b * 8 + w;
        float4 v = reinterpret_cast<const float4*>(stm_V)[row * 32 + lane];
        float sq = v.x*v.x + v.y*v.y + v.z*v.z + v.w*v.w;
        #pragma unroll
        for (int off = 16; off; off >>= 1) sq += __shfl_xor_sync(0xFFFFFFFFu, sq, off);
        float sc = fminf(1.0f, 2.0f / (sqrtf(sq) + 1e-8f));
        reinterpret_cast<float4*>(oSV)[row * 32 + lane] =
            make_float4(v.x*sc, v.y*sc, v.z*sc, v.w*sc);
    }
}

// ---- 1: ltm_K normalize + active compaction (fp32 + bf16) | stm histogram --
__global__ void k_histlkn(const float* __restrict__ ltm_K, const int* __restrict__ ltm_act,
                          const float* __restrict__ stm_h, const int* __restrict__ stm_act) {
    __shared__ float part[8];
    __shared__ int sact[4];
    __shared__ int sbase;
    int tid = threadIdx.x;
    int g = tid >> 6, c = tid & 63, wid = tid >> 5, lane = tid & 31;
    int j = blockIdx.x * 4 + g;
    float v = ltm_K[(size_t)j * 64 + c];
    float sq = v * v;
    #pragma unroll
    for (int off = 16; off; off >>= 1) sq += __shfl_xor_sync(0xFFFFFFFFu, sq, off);
    if (lane == 0) part[wid] = sq;
    int a = (ltm_act[j] > 0) ? 1 : 0;
    if (c == 0) sact[g] = a;
    __syncthreads();
    if (tid == 0) {
        int tot = sact[0] + sact[1] + sact[2] + sact[3];
        sbase = tot ? atomicAdd(&g_scal[4], tot) : 0;
    }
    __syncthreads();
    if (a) {
        int off = 0;
        #pragma unroll
        for (int x = 0; x < 4; ++x) if (x < g) off += sact[x];
        int pos = sbase + off;
        float tot = part[g * 2] + part[g * 2 + 1];
        float nv = v / (sqrtf(tot) + 1e-8f);
        g_lknC[(size_t)pos * 64 + c] = nv;
        g_lknB[(size_t)pos * 64 + c] = __float2bfloat16(nv);
        if (c == 0) g_ajinv[pos] = 0xFFFFFFFFu - (unsigned)j;
    }
    int i = blockIdx.x * 256 + tid;
    if (i < N_STM && stm_act[i] > 0) atomicAdd(&g_hist[hbin(stm_h[i])], 1);
}

// ---- 2: block 0 = threshold+pad+compaction+tie-break; block 1 = freeslots --
__global__ void k_prep(const float* __restrict__ fat, float* __restrict__ oF,
                       const float* __restrict__ h, const int* __restrict__ act,
                       const int* __restrict__ ltm_act) {
    int t = threadIdx.x;
    if (blockIdx.x == 1) {
        // first TOP_M inactive slots (ballot scan, early exit)
        int w = t >> 5, lane = t & 31;
        __shared__ int wcnt[32];
        int running = 0;
        for (int tile = 0; tile < 64 && running < TOP_M; ++tile) {
            int i = tile * 1024 + t;
            int inact = (ltm_act[i] == 0);
            unsigned bal = __ballot_sync(0xFFFFFFFFu, inact);
            if (lane == 0) wcnt[w] = __popc(bal);
            __syncthreads();
            int pre = 0, total = 0;
            #pragma unroll
            for (int x = 0; x < 32; ++x) {
                int cx = wcnt[x];
                if (x < w) pre += cx;
                total += cx;
            }
            int pos = running + pre + __popc(bal & ((1u << lane) - 1));
            if (inact && pos < TOP_M) g_free[pos] = i;
            running += total;
            __syncthreads();
        }
        return;
    }
    __shared__ int s[1024];
    __shared__ int sT, sCnt, ssel, sbnd;
    int base = NBIN - 1 - 4 * t;
    int h0 = g_hist[base], h1 = g_hist[base-1], h2 = g_hist[base-2], h3 = g_hist[base-3];
    g_hist[base] = 0; g_hist[base-1] = 0; g_hist[base-2] = 0; g_hist[base-3] = 0;
    int sum = h0 + h1 + h2 + h3;
    s[t] = sum;
    if (t == 0) { ssel = 0; sbnd = 0; }
    __syncthreads();
    for (int off = 1; off < 1024; off <<= 1) {
        int v = s[t], a2 = (t >= off) ? s[t - off] : 0;
        __syncthreads(); s[t] = v + a2; __syncthreads();
    }
    int c = s[t] - sum;
    int hh[4] = {h0, h1, h2, h3};
    #pragma unroll
    for (int q = 0; q < 4; ++q) {
        if (c < TOP_M && c + hh[q] >= TOP_M) { sT = base - q; sCnt = c; }
        c += hh[q];
    }
    int n_act = g_scal[4];
    for (int idx = t; idx < 128 * 64; idx += 1024) {
        g_lknC[(size_t)n_act * 64 + idx] = 0.0f;
        g_lknB[(size_t)n_act * 64 + idx] = __float2bfloat16(0.0f);
    }
    if (t < 128) g_ajinv[n_act + t] = 0u;
    if (t == 0) {
        g_scal[5] = (n_act + 127) >> 7;
        oF[0] = 0.2f * fat[0];
    }
    __syncthreads();
    int T = sT;
    for (int b2 = 0; b2 < N_STM; b2 += 4096) {
        int ia[4]; float ha[4];
        #pragma unroll
        for (int q = 0; q < 4; ++q) {
            int i = b2 + q * 1024 + t;
            ia[q] = act[i]; ha[q] = h[i];
        }
        #pragma unroll
        for (int q = 0; q < 4; ++q) {
            if (ia[q] > 0) {
                int bn = hbin(ha[q]);
                int i = b2 + q * 1024 + t;
                if (bn > T)       g_sel[atomicAdd(&ssel, 1)] = i;
                else if (bn == T) g_boundary[atomicAdd(&sbnd, 1)] = i;
            }
        }
    }
    __syncthreads();
    int B = sbnd, need = TOP_M - sCnt;
    for (int cc = t; cc < B; cc += 1024) {
        int i = g_boundary[cc];
        unsigned long long k = stm_key(i, h[i]);
        int r = 0;
        for (int q = 0; q < B; ++q) {
            int i2 = g_boundary[q];
            r += (stm_key(i2, h[i2]) > k);
        }
        if (r < need) g_sel[atomicAdd(&ssel, 1)] = i;
    }
    __syncthreads();
    if (t == 0) g_scal[4] = 0;   // restore for graph replay
}

// ---- 3: projection + kp normalize (fp32 + bf16) ----------------------------
__global__ void k_proj(const float* __restrict__ stm_K, const float* __restrict__ stm_h,
                       const float* __restrict__ W, const float* __restrict__ b) {
    int m = blockIdx.x, c = threadIdx.x;
    __shared__ float sK[16];
    __shared__ float ws[2];
    int s = g_sel[m];
    if (c < 16) sK[c] = stm_K[(size_t)s * 16 + c];
    __syncthreads();
    float acc = b[c];
    #pragma unroll
    for (int k = 0; k < 16; ++k) acc = fmaf(sK[k], W[k * 64 + c], acc);
    float sq = acc * acc;
    #pragma unroll
    for (int off = 16; off; off >>= 1) sq += __shfl_xor_sync(0xFFFFFFFFu, sq, off);
    if ((c & 31) == 0) ws[c >> 5] = sq;
    __syncthreads();
    float kpv = acc / (sqrtf(ws[0] + ws[1]) + 1e-8f);
    g_Kproj[m * 64 + c] = acc;
    g_kpN[m * 64 + c] = kpv;
    g_kpB[m * 64 + c] = __float2bfloat16(kpv);
    if (c == 0) g_omega[m] = 0.05f * stm_h[s];
}

// ---- 4 (S1): bf16 HMMA screen with paired-k smem layout --------------------
// Row stride 40 u32 (160B, =8 mod 32 banks): quad-rows hit disjoint bank
// groups; k-pairs (k, k+8) adjacent -> each frag load is one LDS.64.
__global__ void __launch_bounds__(256) k_simsT() {
    __shared__ __align__(16) unsigned sA32[64 * 40];
    __shared__ __align__(16) unsigned sB32[128 * 40];
    __shared__ unsigned s_max[64];
    const int tid = threadIdx.x, wid = tid >> 5, l = tid & 31;
    const int warp_m = wid >> 2, warp_n = wid & 3;
    const int m0 = blockIdx.x * 64;
    const int ns = g_scal[5];

    {   // A fill: 64 rows x 32 u32, permuted
        const unsigned* src = (const unsigned*)(g_kpB + (size_t)m0 * 64);
        #pragma unroll
        for (int i = 0; i < 8; ++i) {
            int idx = tid + i * 256;
            int row = idx >> 5, cu = idx & 31;
            sA32[row * 40 + kperm(cu)] = src[idx];
        }
    }

    float runmax = -3.0f;

    for (int t = blockIdx.y; t < ns; t += (int)gridDim.y) {
        __syncthreads();
        {
            const unsigned* src = (const unsigned*)(g_lknB + (size_t)t * 128 * 64);
            #pragma unroll
            for (int i = 0; i < 16; ++i) {
                int idx = tid + i * 256;
                int row = idx >> 5, cu = idx & 31;
                sB32[row * 40 + kperm(cu)] = __ldg(&src[idx]);
            }
        }
        if (tid < 64) s_max[tid] = 0u;
        __syncthreads();

        float acc[2][4][4];
        #pragma unroll
        for (int i = 0; i < 2; ++i)
            #pragma unroll
            for (int q = 0; q < 4; ++q)
                #pragma unroll
                for (int r = 0; r < 4; ++r) acc[i][q][r] = 0.0f;

        #pragma unroll
        for (int ch = 0; ch < 4; ++ch) {
            unsigned a[2][4], b[4][2];
            int cb = ch * 8 + (l & 3) * 2;
            #pragma unroll
            for (int i = 0; i < 2; ++i) {
                int r0 = warp_m * 32 + i * 16 + (l >> 2);
                unsigned long long v0 =
                    *reinterpret_cast<const unsigned long long*>(&sA32[r0 * 40 + cb]);
                unsigned long long v1 =
                    *reinterpret_cast<const unsigned long long*>(&sA32[(r0 + 8) * 40 + cb]);
                a[i][0] = (unsigned)v0; a[i][2] = (unsigned)(v0 >> 32);
                a[i][1] = (unsigned)v1; a[i][3] = (unsigned)(v1 >> 32);
            }
            #pragma unroll
            for (int q = 0; q < 4; ++q) {
                int rb = warp_n * 32 + q * 8 + (l >> 2);
                unsigned long long v =
                    *reinterpret_cast<const unsigned long long*>(&sB32[rb * 40 + cb]);
                b[q][0] = (unsigned)v; b[q][1] = (unsigned)(v >> 32);
            }
            #pragma unroll
            for (int i = 0; i < 2; ++i)
                #pragma unroll
                for (int q = 0; q < 4; ++q)
                    mma16816(acc[i][q], a[i], b[q]);
        }

        #pragma unroll
        for (int i = 0; i < 2; ++i) {
            float t0 = -3.0f, t1 = -3.0f;
            #pragma unroll
            for (int q = 0; q < 4; ++q) {
                t0 = fmaxf(t0, fmaxf(acc[i][q][0], acc[i][q][1]));
                t1 = fmaxf(t1, fmaxf(acc[i][q][2], acc[i][q][3]));
            }
            t0 = fmaxf(t0, __shfl_xor_sync(0xFFFFFFFFu, t0, 1));
            t0 = fmaxf(t0, __shfl_xor_sync(0xFFFFFFFFu, t0, 2));
            t1 = fmaxf(t1, __shfl_xor_sync(0xFFFFFFFFu, t1, 1));
            t1 = fmaxf(t1, __shfl_xor_sync(0xFFFFFFFFu, t1, 2));
            if ((l & 3) == 0) {
                int r0 = warp_m * 32 + i * 16 + (l >> 2);
                atomicMax(&s_max[r0], fmono(t0));
                atomicMax(&s_max[r0 + 8], fmono(t1));
            }
        }
        __syncthreads();
        if (tid < 64) {
            float v = funmono(s_max[tid]);
            g_smax[(size_t)(m0 + tid) * NSMAX + t] = v;
            runmax = fmaxf(runmax, v);
        }
    }
    if (tid < 64) atomicMax(&g_gmaxU[m0 + tid], fmono(runmax));
}

// ---- 5 (S2): exact fp32 recheck of candidate stages -> g_best --------------
__global__ void k_exact() {
    int wid = threadIdx.x >> 5, lane = threadIdx.x & 31;
    int m = blockIdx.x * 8 + wid;
    int ns = g_scal[5];
    float thr = funmono(g_gmaxU[m]) - 0.02f;
    float4 kp4[16];
    const float4* kpr = reinterpret_cast<const float4*>(g_kpN + m * 64);
    #pragma unroll
    for (int i = 0; i < 16; ++i) kp4[i] = kpr[i];
    unsigned long long best = 0ull;
    for (int t = 0; t < ns; ++t) {
        if (g_smax[(size_t)m * NSMAX + t] < thr) continue;
        #pragma unroll
        for (int q = 0; q < 4; ++q) {
            int j = t * 128 + lane + q * 32;
            const float4* br = reinterpret_cast<const float4*>(g_lknC + (size_t)j * 64);
            float dot = 0.f;
            #pragma unroll
            for (int i = 0; i < 16; ++i) {
                float4 b4 = br[i];
                dot = fmaf(kp4[i].x, b4.x, dot);
                dot = fmaf(kp4[i].y, b4.y, dot);
                dot = fmaf(kp4[i].z, b4.z, dot);
                dot = fmaf(kp4[i].w, b4.w, dot);
            }
            unsigned long long pk =
                ((unsigned long long)fmono(dot) << 32) | g_ajinv[j];
            if (pk > best) best = pk;
        }
    }
    #pragma unroll
    for (int off = 16; off; off >>= 1) {
        unsigned long long o = __shfl_xor_sync(0xFFFFFFFFu, best, off);
        if (o > best) best = o;
    }
    if (lane == 0) { g_best[m] = best; g_gmaxU[m] = 0u; }  // reset for replay
}

// ---- 6: matched scatter-add -------------------------------------------------
__global__ void k_matched(const float* __restrict__ stm_V, const float* __restrict__ stm_e,
                          const float* __restrict__ stm_h,
                          float* __restrict__ oK, float* __restrict__ oV,
                          float* __restrict__ oe, float* __restrict__ oh) {
    int m = blockIdx.x, c = threadIdx.x;
    unsigned long long p = g_best[m];
    float sim = funmono((unsigned)(p >> 32));
    int j = (int)(0xFFFFFFFFu - (unsigned)(p & 0xFFFFFFFFull));
    bool matched = (sim >= 0.5f);
    int s = g_sel[m];
    float om = g_omega[m];
    if (c == 0) {
        g_unm[m] = matched ? 0 : 1;
        g_key[m] = stm_key(s, stm_h[s]);
        if (matched) atomicAdd(&oh[j], om);
    }
    if (matched) {
        atomicAdd(&oK[(size_t)j * 64 + c], om * g_Kproj[m * 64 + c]);
        atomicAdd(&oV[(size_t)j * 128 + c], om * stm_V[(size_t)s * 128 + c]);
        atomicAdd(&oV[(size_t)j * 128 + 64 + c], om * stm_V[(size_t)s * 128 + 64 + c]);
        if (c < 4) atomicAdd(&oe[(size_t)j * 4 + c], om * stm_e[(size_t)s * 4 + c]);
    }
}

// ---- 7: rank unmatched + fresh-slot writes (merged) -------------------------
__global__ void k_ru(const float* __restrict__ stm_V, const float* __restrict__ stm_e,
                     float* __restrict__ oK, float* __restrict__ oV,
                     float* __restrict__ oe, float* __restrict__ oh) {
    __shared__ unsigned long long sk[TOP_M];
    __shared__ unsigned char su[TOP_M];
    __shared__ int sslot[256];
    int t = threadIdx.x;
    for (int i = t; i < TOP_M; i += 256) { sk[i] = g_key[i]; su[i] = (unsigned char)g_unm[i]; }
    __syncthreads();
    int m = blockIdx.x * 256 + t;
    int slot = -1;
    if (su[m]) {
        unsigned long long k = sk[m];
        int r = 0;
        for (int i = 0; i < TOP_M; ++i) r += (su[i] && sk[i] > k);
        slot = g_free[r];
    }
    sslot[t] = slot;
    __syncthreads();
    for (int mm = 0; mm < 256; ++mm) {
        int sl = sslot[mm];
        if (sl < 0) continue;
        int gm = blockIdx.x * 256 + mm;
        int s = g_sel[gm];
        if (t < 64)       oK[(size_t)sl * 64 + t] = g_Kproj[gm * 64 + t];
        else if (t < 192) oV[(size_t)sl * 128 + (t - 64)] = stm_V[(size_t)s * 128 + (t - 64)];
        else if (t < 196) oe[(size_t)sl * 4 + (t - 192)] = stm_e[(size_t)s * 4 + (t - 192)];
        else if (t == 196) oh[sl] = g_omega[gm];
    }
}

// ---- fused 3D gaussian blur + merge (branchless, div-free) -------------------
#define BLUR_SMEM ((10368 + 10368) * 4)   // 82944 B
__global__ void __launch_bounds__(256) k_blurAll(const float* __restrict__ stm_t,
                                                 const float* __restrict__ ltm_t,
                                                 float* __restrict__ oT) {
    extern __shared__ float p[];
    float* p0 = p;
    float* p0c = p + 576;
    float* p1 = p + 10368;
    float w[7], inv; gw(w, inv);
    int tid = threadIdx.x;
    int plane = blockIdx.x;
    int c = plane / 96, d = plane % 96;
    size_t cbase = (size_t)c * 96 * 9216;

    for (int i = tid; i < 576; i += 256) { p0[i] = 0.0f; p0[9792 + i] = 0.0f; }
    for (int i = tid; i < 1152; i += 256) {
        int row = i / 12, cc = i - row * 12;
        p1[row * 108 + (cc < 6 ? cc : 96 + cc)] = 0.0f;
    }

    float4 acc[9];
    #pragma unroll
    for (int e = 0; e < 9; ++e) acc[e] = make_float4(0.f, 0.f, 0.f, 0.f);
    #pragma unroll
    for (int t = -6; t <= 6; ++t) {
        int dd = d + t;
        if (dd < 0 || dd >= 96) continue;
        float ww = w[t < 0 ? -t : t];
        const float4* src = reinterpret_cast<const float4*>(stm_t + cbase + (size_t)dd * 9216);
        #pragma unroll
        for (int e = 0; e < 9; ++e) {
            float4 v = src[tid + e * 256];
            acc[e].x = fmaf(v.x, ww, acc[e].x);
            acc[e].y = fmaf(v.y, ww, acc[e].y);
            acc[e].z = fmaf(v.z, ww, acc[e].z);
            acc[e].w = fmaf(v.w, ww, acc[e].w);
        }
    }
    float4* d0 = reinterpret_cast<float4*>(p0c);
    #pragma unroll
    for (int e = 0; e < 9; ++e) {
        float4 v = acc[e];
        d0[tid + e * 256] = make_float4(v.x * inv, v.y * inv, v.z * inv, v.w * inv);
    }
    __syncthreads();

    {
        int h = tid / 96;
        int x = tid - h * 96;
        for (int i = tid; i < 9216; i += 256) {
            float a2 = p0c[i] * w[0];
            #pragma unroll
            for (int t = 1; t < 7; ++t)
                a2 += (p0c[i - t * 96] + p0c[i + t * 96]) * w[t];
            p1[h * 108 + 6 + x] = a2 * inv;
            x += 64; h += 2;
            if (x >= 96) { x -= 96; h += 1; }
        }
    }
    __syncthreads();

    {
        float xi = (c == 0) ? 0.005f : 0.003f;
        size_t base = cbase + (size_t)d * 9216;
        int h = tid / 96;
        int x = tid - h * 96;
        for (int i = tid; i < 9216; i += 256) {
            const float* row = p1 + h * 108 + 6 + x;
            float a2 = row[0] * w[0];
            #pragma unroll
            for (int t = 1; t < 7; ++t)
                a2 += (row[-t] + row[t]) * w[t];
            oT[base + i] = ltm_t[base + i] + xi * (a2 * inv);
            x += 64; h += 2;
            if (x >= 96) { x -= 96; h += 1; }
        }
    }
}

extern "C" void kernel_launch(void* const* d_in, const int* in_sizes, int n_in,
                              void* d_out, int out_size) {
    (void)in_sizes; (void)n_in; (void)out_size;
    const float* stm_K   = (const float*)d_in[0];
    const float* stm_V   = (const float*)d_in[1];
    const float* stm_e   = (const float*)d_in[2];
    const float* stm_h   = (const float*)d_in[3];
    const float* ltm_K   = (const float*)d_in[4];
    const float* ltm_V   = (const float*)d_in[5];
    const float* ltm_e   = (const float*)d_in[6];
    const float* ltm_h   = (const float*)d_in[7];
    const float* W       = (const float*)d_in[8];
    const float* b       = (const float*)d_in[9];
    const float* stm_t   = (const float*)d_in[10];
    const float* ltm_t   = (const float*)d_in[11];
    const float* fatigue = (const float*)d_in[12];
    const int*   stm_act = (const int*)d_in[13];
    const int*   ltm_act = (const int*)d_in[14];

    float* out = (float*)d_out;
    float* oK  = out;                 // 65536*64
    float* oV  = out + 4194304;       // 65536*128
    float* oe  = out + 12582912;      // 65536*4
    float* oh  = out + 12845056;      // 65536
    float* oSV = out + 12910592;      // 65536*128
    float* oT  = out + 21299200;      // 5*96^3
    float* oF  = out + 25722880;      // 1

    static cudaStream_t sB = 0, sD = 0;
    static cudaEvent_t eR = 0, eB = 0, eD = 0;
    static bool init_done = false;
    if (!init_done) {
        cudaFuncSetAttribute(k_blurAll, cudaFuncAttributeMaxDynamicSharedMemorySize, BLUR_SMEM);
        cudaStreamCreateWithFlags(&sB, cudaStreamNonBlocking);
        cudaStreamCreateWithFlags(&sD, cudaStreamNonBlocking);
        cudaEventCreateWithFlags(&eR, cudaEventDisableTiming);
        cudaEventCreateWithFlags(&eB, cudaEventDisableTiming);
        cudaEventCreateWithFlags(&eD, cudaEventDisableTiming);
        init_done = true;
    }

    // fork
    cudaEventRecord(eR, 0);
    cudaStreamWaitEvent(sB, eR, 0);
    cudaStreamWaitEvent(sD, eR, 0);

    // critical path first (k_simsT = launch #4 for ncu)
    k_histlkn<<<16384, 256>>>(ltm_K, ltm_act, stm_h, stm_act);
    k_prep<<<2, 1024>>>(fatigue, oF, stm_h, stm_act, ltm_act);
    k_proj<<<2048, 64>>>(stm_K, stm_h, W, b);
    k_simsT<<<dim3(32, 9), 256>>>();
    k_exact<<<256, 256>>>();

    // side chain B: base copy + stm_V clip (one kernel)
    k_side<<<20800, 256, 0, sB>>>((const float4*)ltm_K, (const float4*)ltm_V,
                                  (const float4*)ltm_e, (const float4*)ltm_h,
                                  (float4*)oK, stm_V, oSV);
    cudaEventRecord(eB, sB);

    // side chain D: fused terrain blur + merge
    k_blurAll<<<480, 256, BLUR_SMEM, sD>>>(stm_t, ltm_t, oT);
    cudaEventRecord(eD, sD);

    // tail of critical path
    cudaStreamWaitEvent(0, eB, 0);
    k_matched<<<2048, 64>>>(stm_V, stm_e, stm_h, oK, oV, oe, oh);
    k_ru<<<8, 256>>>(stm_V, stm_e, oK, oV, oe, oh);

    // join remaining side chain
    cudaStreamWaitEvent(0, eD, 0);
}

// round 13
// speedup vs baseline: 1.3493x; 1.3493x over previous
#include <cuda_runtime.h>
#include <cuda_bf16.h>
#include <cstdint>
#include <math.h>

#define N_STM 65536
#define N_LTM 65536
#define TOP_M 2048
#define NBIN  4096
#define TVOL  (5*96*96*96)
#define NSMAX 516

// ---------------- scratch (static zero-init; replay-safe) -------------------
__device__ int                g_hist[NBIN];
__device__ int                g_scal[8];   // 4:n_act 5:n_stages
__device__ int                g_sel[TOP_M];
__device__ int                g_boundary[N_STM];
__device__ float              g_Kproj[TOP_M*64];
__device__ float              g_kpN[TOP_M*64];
__device__ __align__(16) __nv_bfloat16 g_kpB[TOP_M*64];
__device__ float              g_omega[TOP_M];
__device__ float              g_lknC[(size_t)(N_LTM+128)*64];
__device__ __align__(16) __nv_bfloat16 g_lknB[(size_t)(N_LTM+128)*64];
__device__ unsigned           g_ajinv[N_LTM+128];
__device__ float              g_smax[(size_t)TOP_M*NSMAX];
__device__ unsigned           g_gmaxU[TOP_M];
__device__ unsigned long long g_best[TOP_M];
__device__ unsigned long long g_key[TOP_M];
__device__ int                g_unm[TOP_M];
__device__ int                g_rank[TOP_M];
__device__ int                g_free[TOP_M];

// ---------------- helpers ---------------------------------------------------
__device__ __forceinline__ unsigned fmono(float f) {
    unsigned u = __float_as_uint(f);
    return (u & 0x80000000u) ? ~u : (u | 0x80000000u);
}
__device__ __forceinline__ float funmono(unsigned m) {
    unsigned u = (m & 0x80000000u) ? (m ^ 0x80000000u) : ~m;
    return __uint_as_float(u);
}
__device__ __forceinline__ unsigned long long stm_key(int i, float h) {
    return ((unsigned long long)__float_as_uint(h) << 32) | (0xFFFFFFFFu - (unsigned)i);
}
__device__ __forceinline__ int hbin(float h) {
    return min(max((int)(h * (float)NBIN), 0), NBIN - 1);
}
__device__ __forceinline__ void gw(float* w, float& inv) {
    w[0] = 1.0f; float sum = 1.0f;
    #pragma unroll
    for (int i = 1; i < 7; ++i) {
        w[i] = expf(-0.5f * (float)(i * i) / 4.0f);
        sum += 2.0f * w[i];
    }
    inv = 1.0f / sum;
}
__device__ __forceinline__ void mma16816(float* c, const unsigned* a, const unsigned* b) {
    asm volatile("mma.sync.aligned.m16n8k16.row.col.f32.bf16.bf16.f32 "
                 "{%0,%1,%2,%3}, {%4,%5,%6,%7}, {%8,%9}, {%0,%1,%2,%3};"
                 : "+f"(c[0]), "+f"(c[1]), "+f"(c[2]), "+f"(c[3])
                 : "r"(a[0]), "r"(a[1]), "r"(a[2]), "r"(a[3]), "r"(b[0]), "r"(b[1]));
}
// k-pair permutation: (x, x+4) u32 cols adjacent within each 8-col chunk
__device__ __forceinline__ int kperm(int cu) {
    return (cu & ~7) + ((cu & 3) * 2 + ((cu >> 2) & 1));
}

// ---- side: base-state copy (ltm->out head) + stm_V norm clip ---------------
__global__ void k_side(const float4* __restrict__ K, const float4* __restrict__ V,
                       const float4* __restrict__ e, const float4* __restrict__ h,
                       float4* __restrict__ out,
                       const float* __restrict__ stm_V, float* __restrict__ oSV) {
    if (blockIdx.x < 12608) {
        int i = blockIdx.x * blockDim.x + threadIdx.x;   // 3227648 total
        float4 v;
        if (i < 1048576)       v = K[i];
        else if (i < 3145728)  v = V[i - 1048576];
        else if (i < 3211264)  v = e[i - 3145728];
        else                   v = h[i - 3211264];
        out[i] = v;
    } else {
        int b = blockIdx.x - 12608;                      // 8192 blocks
        int w = threadIdx.x >> 5, lane = threadIdx.x & 31;
        size_t row = (size_t)b * 8 + w;
        float4 v = reinterpret_cast<const float4*>(stm_V)[row * 32 + lane];
        float sq = v.x*v.x + v.y*v.y + v.z*v.z + v.w*v.w;
        #pragma unroll
        for (int off = 16; off; off >>= 1) sq += __shfl_xor_sync(0xFFFFFFFFu, sq, off);
        float sc = fminf(1.0f, 2.0f / (sqrtf(sq) + 1e-8f));
        reinterpret_cast<float4*>(oSV)[row * 32 + lane] =
            make_float4(v.x*sc, v.y*sc, v.z*sc, v.w*sc);
    }
}

// ---- 1: ltm_K normalize + active compaction (fp32 + bf16) | stm histogram --
__global__ void k_histlkn(const float* __restrict__ ltm_K, const int* __restrict__ ltm_act,
                          const float* __restrict__ stm_h, const int* __restrict__ stm_act) {
    __shared__ float part[8];
    __shared__ int sact[4];
    __shared__ int sbase;
    int tid = threadIdx.x;
    int g = tid >> 6, c = tid & 63, wid = tid >> 5, lane = tid & 31;
    int j = blockIdx.x * 4 + g;
    float v = ltm_K[(size_t)j * 64 + c];
    float sq = v * v;
    #pragma unroll
    for (int off = 16; off; off >>= 1) sq += __shfl_xor_sync(0xFFFFFFFFu, sq, off);
    if (lane == 0) part[wid] = sq;
    int a = (ltm_act[j] > 0) ? 1 : 0;
    if (c == 0) sact[g] = a;
    __syncthreads();
    if (tid == 0) {
        int tot = sact[0] + sact[1] + sact[2] + sact[3];
        sbase = tot ? atomicAdd(&g_scal[4], tot) : 0;
    }
    __syncthreads();
    if (a) {
        int off = 0;
        #pragma unroll
        for (int x = 0; x < 4; ++x) if (x < g) off += sact[x];
        int pos = sbase + off;
        float tot = part[g * 2] + part[g * 2 + 1];
        float nv = v / (sqrtf(tot) + 1e-8f);
        g_lknC[(size_t)pos * 64 + c] = nv;
        g_lknB[(size_t)pos * 64 + c] = __float2bfloat16(nv);
        if (c == 0) g_ajinv[pos] = 0xFFFFFFFFu - (unsigned)j;
    }
    int i = blockIdx.x * 256 + tid;
    if (i < N_STM && stm_act[i] > 0) atomicAdd(&g_hist[hbin(stm_h[i])], 1);
}

// ---- 2: block 0 = threshold+pad+compaction+tie-break; block 1 = freeslots --
__global__ void k_prep(const float* __restrict__ fat, float* __restrict__ oF,
                       const float* __restrict__ h, const int* __restrict__ act,
                       const int* __restrict__ ltm_act) {
    int t = threadIdx.x;
    if (blockIdx.x == 1) {
        int w = t >> 5, lane = t & 31;
        __shared__ int wcnt[32];
        int running = 0;
        for (int tile = 0; tile < 64 && running < TOP_M; ++tile) {
            int i = tile * 1024 + t;
            int inact = (ltm_act[i] == 0);
            unsigned bal = __ballot_sync(0xFFFFFFFFu, inact);
            if (lane == 0) wcnt[w] = __popc(bal);
            __syncthreads();
            int pre = 0, total = 0;
            #pragma unroll
            for (int x = 0; x < 32; ++x) {
                int cx = wcnt[x];
                if (x < w) pre += cx;
                total += cx;
            }
            int pos = running + pre + __popc(bal & ((1u << lane) - 1));
            if (inact && pos < TOP_M) g_free[pos] = i;
            running += total;
            __syncthreads();
        }
        return;
    }
    __shared__ int s[1024];
    __shared__ int sT, sCnt, ssel, sbnd;
    int base = NBIN - 1 - 4 * t;
    int h0 = g_hist[base], h1 = g_hist[base-1], h2 = g_hist[base-2], h3 = g_hist[base-3];
    g_hist[base] = 0; g_hist[base-1] = 0; g_hist[base-2] = 0; g_hist[base-3] = 0;
    int sum = h0 + h1 + h2 + h3;
    s[t] = sum;
    if (t == 0) { ssel = 0; sbnd = 0; }
    __syncthreads();
    for (int off = 1; off < 1024; off <<= 1) {
        int v = s[t], a2 = (t >= off) ? s[t - off] : 0;
        __syncthreads(); s[t] = v + a2; __syncthreads();
    }
    int c = s[t] - sum;
    int hh[4] = {h0, h1, h2, h3};
    #pragma unroll
    for (int q = 0; q < 4; ++q) {
        if (c < TOP_M && c + hh[q] >= TOP_M) { sT = base - q; sCnt = c; }
        c += hh[q];
    }
    int n_act = g_scal[4];
    for (int idx = t; idx < 128 * 64; idx += 1024) {
        g_lknC[(size_t)n_act * 64 + idx] = 0.0f;
        g_lknB[(size_t)n_act * 64 + idx] = __float2bfloat16(0.0f);
    }
    if (t < 128) g_ajinv[n_act + t] = 0u;
    if (t == 0) {
        g_scal[5] = (n_act + 127) >> 7;
        oF[0] = 0.2f * fat[0];
    }
    __syncthreads();
    int T = sT;
    for (int b2 = 0; b2 < N_STM; b2 += 4096) {
        int ia[4]; float ha[4];
        #pragma unroll
        for (int q = 0; q < 4; ++q) {
            int i = b2 + q * 1024 + t;
            ia[q] = act[i]; ha[q] = h[i];
        }
        #pragma unroll
        for (int q = 0; q < 4; ++q) {
            if (ia[q] > 0) {
                int bn = hbin(ha[q]);
                int i = b2 + q * 1024 + t;
                if (bn > T)       g_sel[atomicAdd(&ssel, 1)] = i;
                else if (bn == T) g_boundary[atomicAdd(&sbnd, 1)] = i;
            }
        }
    }
    __syncthreads();
    int B = sbnd, need = TOP_M - sCnt;
    for (int cc = t; cc < B; cc += 1024) {
        int i = g_boundary[cc];
        unsigned long long k = stm_key(i, h[i]);
        int r = 0;
        for (int q = 0; q < B; ++q) {
            int i2 = g_boundary[q];
            r += (stm_key(i2, h[i2]) > k);
        }
        if (r < need) g_sel[atomicAdd(&ssel, 1)] = i;
    }
    __syncthreads();
    if (t == 0) g_scal[4] = 0;   // restore for graph replay
}

// ---- 3: projection + kp normalize (fp32 + bf16) ----------------------------
__global__ void k_proj(const float* __restrict__ stm_K, const float* __restrict__ stm_h,
                       const float* __restrict__ W, const float* __restrict__ b) {
    int m = blockIdx.x, c = threadIdx.x;
    __shared__ float sK[16];
    __shared__ float ws[2];
    int s = g_sel[m];
    if (c < 16) sK[c] = stm_K[(size_t)s * 16 + c];
    __syncthreads();
    float acc = b[c];
    #pragma unroll
    for (int k = 0; k < 16; ++k) acc = fmaf(sK[k], W[k * 64 + c], acc);
    float sq = acc * acc;
    #pragma unroll
    for (int off = 16; off; off >>= 1) sq += __shfl_xor_sync(0xFFFFFFFFu, sq, off);
    if ((c & 31) == 0) ws[c >> 5] = sq;
    __syncthreads();
    float kpv = acc / (sqrtf(ws[0] + ws[1]) + 1e-8f);
    g_Kproj[m * 64 + c] = acc;
    g_kpN[m * 64 + c] = kpv;
    g_kpB[m * 64 + c] = __float2bfloat16(kpv);
    if (c == 0) g_omega[m] = 0.05f * stm_h[s];
}

// ---- 4 (S1): bf16 HMMA screen, paired-k smem layout ------------------------
__global__ void __launch_bounds__(256) k_simsT() {
    __shared__ __align__(16) unsigned sA32[64 * 40];
    __shared__ __align__(16) unsigned sB32[128 * 40];
    __shared__ unsigned s_max[64];
    const int tid = threadIdx.x, wid = tid >> 5, l = tid & 31;
    const int warp_m = wid >> 2, warp_n = wid & 3;
    const int m0 = blockIdx.x * 64;
    const int ns = g_scal[5];

    {   // A fill: 64 rows x 32 u32, permuted
        const unsigned* src = (const unsigned*)(g_kpB + (size_t)m0 * 64);
        #pragma unroll
        for (int i = 0; i < 8; ++i) {
            int idx = tid + i * 256;
            int row = idx >> 5, cu = idx & 31;
            sA32[row * 40 + kperm(cu)] = src[idx];
        }
    }

    float runmax = -3.0f;

    for (int t = blockIdx.y; t < ns; t += (int)gridDim.y) {
        __syncthreads();
        {
            const unsigned* src = (const unsigned*)(g_lknB + (size_t)t * 128 * 64);
            #pragma unroll
            for (int i = 0; i < 16; ++i) {
                int idx = tid + i * 256;
                int row = idx >> 5, cu = idx & 31;
                sB32[row * 40 + kperm(cu)] = __ldg(&src[idx]);
            }
        }
        if (tid < 64) s_max[tid] = 0u;
        __syncthreads();

        float acc[2][4][4];
        #pragma unroll
        for (int i = 0; i < 2; ++i)
            #pragma unroll
            for (int q = 0; q < 4; ++q)
                #pragma unroll
                for (int r = 0; r < 4; ++r) acc[i][q][r] = 0.0f;

        #pragma unroll
        for (int ch = 0; ch < 4; ++ch) {
            unsigned a[2][4], b[4][2];
            int cb = ch * 8 + (l & 3) * 2;
            #pragma unroll
            for (int i = 0; i < 2; ++i) {
                int r0 = warp_m * 32 + i * 16 + (l >> 2);
                unsigned long long v0 =
                    *reinterpret_cast<const unsigned long long*>(&sA32[r0 * 40 + cb]);
                unsigned long long v1 =
                    *reinterpret_cast<const unsigned long long*>(&sA32[(r0 + 8) * 40 + cb]);
                a[i][0] = (unsigned)v0; a[i][2] = (unsigned)(v0 >> 32);
                a[i][1] = (unsigned)v1; a[i][3] = (unsigned)(v1 >> 32);
            }
            #pragma unroll
            for (int q = 0; q < 4; ++q) {
                int rb = warp_n * 32 + q * 8 + (l >> 2);
                unsigned long long v =
                    *reinterpret_cast<const unsigned long long*>(&sB32[rb * 40 + cb]);
                b[q][0] = (unsigned)v; b[q][1] = (unsigned)(v >> 32);
            }
            #pragma unroll
            for (int i = 0; i < 2; ++i)
                #pragma unroll
                for (int q = 0; q < 4; ++q)
                    mma16816(acc[i][q], a[i], b[q]);
        }

        #pragma unroll
        for (int i = 0; i < 2; ++i) {
            float t0 = -3.0f, t1 = -3.0f;
            #pragma unroll
            for (int q = 0; q < 4; ++q) {
                t0 = fmaxf(t0, fmaxf(acc[i][q][0], acc[i][q][1]));
                t1 = fmaxf(t1, fmaxf(acc[i][q][2], acc[i][q][3]));
            }
            t0 = fmaxf(t0, __shfl_xor_sync(0xFFFFFFFFu, t0, 1));
            t0 = fmaxf(t0, __shfl_xor_sync(0xFFFFFFFFu, t0, 2));
            t1 = fmaxf(t1, __shfl_xor_sync(0xFFFFFFFFu, t1, 1));
            t1 = fmaxf(t1, __shfl_xor_sync(0xFFFFFFFFu, t1, 2));
            if ((l & 3) == 0) {
                int r0 = warp_m * 32 + i * 16 + (l >> 2);
                atomicMax(&s_max[r0], fmono(t0));
                atomicMax(&s_max[r0 + 8], fmono(t1));
            }
        }
        __syncthreads();
        if (tid < 64) {
            float v = funmono(s_max[tid]);
            g_smax[(size_t)(m0 + tid) * NSMAX + t] = v;
            runmax = fmaxf(runmax, v);
        }
    }
    if (tid < 64) atomicMax(&g_gmaxU[m0 + tid], fmono(runmax));
}

// ---- 5 (S2): exact fp32 recheck of candidate stages -> g_best --------------
__global__ void k_exact() {
    int wid = threadIdx.x >> 5, lane = threadIdx.x & 31;
    int m = blockIdx.x * 8 + wid;
    int ns = g_scal[5];
    float thr = funmono(g_gmaxU[m]) - 0.02f;
    float4 kp4[16];
    const float4* kpr = reinterpret_cast<const float4*>(g_kpN + m * 64);
    #pragma unroll
    for (int i = 0; i < 16; ++i) kp4[i] = kpr[i];
    unsigned long long best = 0ull;
    for (int t = 0; t < ns; ++t) {
        if (g_smax[(size_t)m * NSMAX + t] < thr) continue;
        #pragma unroll
        for (int q = 0; q < 4; ++q) {
            int j = t * 128 + lane + q * 32;
            const float4* br = reinterpret_cast<const float4*>(g_lknC + (size_t)j * 64);
            float dot = 0.f;
            #pragma unroll
            for (int i = 0; i < 16; ++i) {
                float4 b4 = br[i];
                dot = fmaf(kp4[i].x, b4.x, dot);
                dot = fmaf(kp4[i].y, b4.y, dot);
                dot = fmaf(kp4[i].z, b4.z, dot);
                dot = fmaf(kp4[i].w, b4.w, dot);
            }
            unsigned long long pk =
                ((unsigned long long)fmono(dot) << 32) | g_ajinv[j];
            if (pk > best) best = pk;
        }
    }
    #pragma unroll
    for (int off = 16; off; off >>= 1) {
        unsigned long long o = __shfl_xor_sync(0xFFFFFFFFu, best, off);
        if (o > best) best = o;
    }
    if (lane == 0) { g_best[m] = best; g_gmaxU[m] = 0u; }  // reset for replay
}

// ---- 6: matched scatter-add -------------------------------------------------
__global__ void k_matched(const float* __restrict__ stm_V, const float* __restrict__ stm_e,
                          const float* __restrict__ stm_h,
                          float* __restrict__ oK, float* __restrict__ oV,
                          float* __restrict__ oe, float* __restrict__ oh) {
    int m = blockIdx.x, c = threadIdx.x;
    unsigned long long p = g_best[m];
    float sim = funmono((unsigned)(p >> 32));
    int j = (int)(0xFFFFFFFFu - (unsigned)(p & 0xFFFFFFFFull));
    bool matched = (sim >= 0.5f);
    int s = g_sel[m];
    float om = g_omega[m];
    if (c == 0) {
        g_unm[m] = matched ? 0 : 1;
        g_key[m] = stm_key(s, stm_h[s]);
        if (matched) atomicAdd(&oh[j], om);
    }
    if (matched) {
        atomicAdd(&oK[(size_t)j * 64 + c], om * g_Kproj[m * 64 + c]);
        atomicAdd(&oV[(size_t)j * 128 + c], om * stm_V[(size_t)s * 128 + c]);
        atomicAdd(&oV[(size_t)j * 128 + 64 + c], om * stm_V[(size_t)s * 128 + 64 + c]);
        if (c < 4) atomicAdd(&oe[(size_t)j * 4 + c], om * stm_e[(size_t)s * 4 + c]);
    }
}

// ---- 7: rank unmatched (h desc, idx asc) -------------------------------------
__global__ void k_rank() {
    __shared__ unsigned long long sk[TOP_M];
    __shared__ unsigned char su[TOP_M];
    int t = threadIdx.x;
    for (int i = t; i < TOP_M; i += 256) { sk[i] = g_key[i]; su[i] = (unsigned char)g_unm[i]; }
    __syncthreads();
    int m = blockIdx.x * 256 + t;
    if (g_unm[m]) {
        unsigned long long k = sk[m];
        int r = 0;
        for (int i = 0; i < TOP_M; ++i) r += (su[i] && sk[i] > k);
        g_rank[m] = r;
    }
}

// ---- 8: unmatched fresh-slot writes (2048-way parallel) ----------------------
__global__ void k_unmatch(const float* __restrict__ stm_V, const float* __restrict__ stm_e,
                          float* __restrict__ oK, float* __restrict__ oV,
                          float* __restrict__ oe, float* __restrict__ oh) {
    int m = blockIdx.x;
    if (!g_unm[m]) return;
    int slot = g_free[g_rank[m]], c = threadIdx.x, s = g_sel[m];
    oK[(size_t)slot * 64 + c] = g_Kproj[m * 64 + c];
    oV[(size_t)slot * 128 + c] = stm_V[(size_t)s * 128 + c];
    oV[(size_t)slot * 128 + 64 + c] = stm_V[(size_t)s * 128 + 64 + c];
    if (c < 4) oe[(size_t)slot * 4 + c] = stm_e[(size_t)s * 4 + c];
    if (c == 0) oh[slot] = g_omega[m];
}

// ---- fused 3D gaussian blur + merge (branchless, div-free) -------------------
#define BLUR_SMEM ((10368 + 10368) * 4)   // 82944 B
__global__ void __launch_bounds__(256) k_blurAll(const float* __restrict__ stm_t,
                                                 const float* __restrict__ ltm_t,
                                                 float* __restrict__ oT) {
    extern __shared__ float p[];
    float* p0 = p;
    float* p0c = p + 576;
    float* p1 = p + 10368;
    float w[7], inv; gw(w, inv);
    int tid = threadIdx.x;
    int plane = blockIdx.x;
    int c = plane / 96, d = plane % 96;
    size_t cbase = (size_t)c * 96 * 9216;

    for (int i = tid; i < 576; i += 256) { p0[i] = 0.0f; p0[9792 + i] = 0.0f; }
    for (int i = tid; i < 1152; i += 256) {
        int row = i / 12, cc = i - row * 12;
        p1[row * 108 + (cc < 6 ? cc : 96 + cc)] = 0.0f;
    }

    float4 acc[9];
    #pragma unroll
    for (int e = 0; e < 9; ++e) acc[e] = make_float4(0.f, 0.f, 0.f, 0.f);
    #pragma unroll
    for (int t = -6; t <= 6; ++t) {
        int dd = d + t;
        if (dd < 0 || dd >= 96) continue;
        float ww = w[t < 0 ? -t : t];
        const float4* src = reinterpret_cast<const float4*>(stm_t + cbase + (size_t)dd * 9216);
        #pragma unroll
        for (int e = 0; e < 9; ++e) {
            float4 v = src[tid + e * 256];
            acc[e].x = fmaf(v.x, ww, acc[e].x);
            acc[e].y = fmaf(v.y, ww, acc[e].y);
            acc[e].z = fmaf(v.z, ww, acc[e].z);
            acc[e].w = fmaf(v.w, ww, acc[e].w);
        }
    }
    float4* d0 = reinterpret_cast<float4*>(p0c);
    #pragma unroll
    for (int e = 0; e < 9; ++e) {
        float4 v = acc[e];
        d0[tid + e * 256] = make_float4(v.x * inv, v.y * inv, v.z * inv, v.w * inv);
    }
    __syncthreads();

    {
        int h = tid / 96;
        int x = tid - h * 96;
        for (int i = tid; i < 9216; i += 256) {
            float a2 = p0c[i] * w[0];
            #pragma unroll
            for (int t = 1; t < 7; ++t)
                a2 += (p0c[i - t * 96] + p0c[i + t * 96]) * w[t];
            p1[h * 108 + 6 + x] = a2 * inv;
            x += 64; h += 2;
            if (x >= 96) { x -= 96; h += 1; }
        }
    }
    __syncthreads();

    {
        float xi = (c == 0) ? 0.005f : 0.003f;
        size_t base = cbase + (size_t)d * 9216;
        int h = tid / 96;
        int x = tid - h * 96;
        for (int i = tid; i < 9216; i += 256) {
            const float* row = p1 + h * 108 + 6 + x;
            float a2 = row[0] * w[0];
            #pragma unroll
            for (int t = 1; t < 7; ++t)
                a2 += (row[-t] + row[t]) * w[t];
            oT[base + i] = ltm_t[base + i] + xi * (a2 * inv);
            x += 64; h += 2;
            if (x >= 96) { x -= 96; h += 1; }
        }
    }
}

extern "C" void kernel_launch(void* const* d_in, const int* in_sizes, int n_in,
                              void* d_out, int out_size) {
    (void)in_sizes; (void)n_in; (void)out_size;
    const float* stm_K   = (const float*)d_in[0];
    const float* stm_V   = (const float*)d_in[1];
    const float* stm_e   = (const float*)d_in[2];
    const float* stm_h   = (const float*)d_in[3];
    const float* ltm_K   = (const float*)d_in[4];
    const float* ltm_V   = (const float*)d_in[5];
    const float* ltm_e   = (const float*)d_in[6];
    const float* ltm_h   = (const float*)d_in[7];
    const float* W       = (const float*)d_in[8];
    const float* b       = (const float*)d_in[9];
    const float* stm_t   = (const float*)d_in[10];
    const float* ltm_t   = (const float*)d_in[11];
    const float* fatigue = (const float*)d_in[12];
    const int*   stm_act = (const int*)d_in[13];
    const int*   ltm_act = (const int*)d_in[14];

    float* out = (float*)d_out;
    float* oK  = out;                 // 65536*64
    float* oV  = out + 4194304;       // 65536*128
    float* oe  = out + 12582912;      // 65536*4
    float* oh  = out + 12845056;      // 65536
    float* oSV = out + 12910592;      // 65536*128
    float* oT  = out + 21299200;      // 5*96^3
    float* oF  = out + 25722880;      // 1

    static cudaStream_t sB = 0, sD = 0;
    static cudaEvent_t eR = 0, eB = 0, eD = 0;
    static bool init_done = false;
    if (!init_done) {
        cudaFuncSetAttribute(k_blurAll, cudaFuncAttributeMaxDynamicSharedMemorySize, BLUR_SMEM);
        cudaStreamCreateWithFlags(&sB, cudaStreamNonBlocking);
        cudaStreamCreateWithFlags(&sD, cudaStreamNonBlocking);
        cudaEventCreateWithFlags(&eR, cudaEventDisableTiming);
        cudaEventCreateWithFlags(&eB, cudaEventDisableTiming);
        cudaEventCreateWithFlags(&eD, cudaEventDisableTiming);
        init_done = true;
    }

    // fork
    cudaEventRecord(eR, 0);
    cudaStreamWaitEvent(sB, eR, 0);
    cudaStreamWaitEvent(sD, eR, 0);

    // critical path first (k_simsT = launch #4 for ncu)
    k_histlkn<<<16384, 256>>>(ltm_K, ltm_act, stm_h, stm_act);
    k_prep<<<2, 1024>>>(fatigue, oF, stm_h, stm_act, ltm_act);
    k_proj<<<2048, 64>>>(stm_K, stm_h, W, b);
    k_simsT<<<dim3(32, 18), 256>>>();
    k_exact<<<256, 256>>>();

    // side chain B: base copy + stm_V clip (one kernel)
    k_side<<<20800, 256, 0, sB>>>((const float4*)ltm_K, (const float4*)ltm_V,
                                  (const float4*)ltm_e, (const float4*)ltm_h,
                                  (float4*)oK, stm_V, oSV);
    cudaEventRecord(eB, sB);

    // side chain D: fused terrain blur + merge
    k_blurAll<<<480, 256, BLUR_SMEM, sD>>>(stm_t, ltm_t, oT);
    cudaEventRecord(eD, sD);

    // tail of critical path
    cudaStreamWaitEvent(0, eB, 0);
    k_matched<<<2048, 64>>>(stm_V, stm_e, stm_h, oK, oV, oe, oh);
    k_rank<<<8, 256>>>();
    k_unmatch<<<2048, 64>>>(stm_V, stm_e, oK, oV, oe, oh);

    // join remaining side chain
    cudaStreamWaitEvent(0, eD, 0);
}

// round 14
// speedup vs baseline: 1.6552x; 1.2267x over previous
#include <cuda_runtime.h>
#include <cuda_bf16.h>
#include <cstdint>
#include <math.h>

#define N_STM 65536
#define N_LTM 65536
#define TOP_M 2048
#define NBIN  4096
#define TVOL  (5*96*96*96)
#define NSMAX 516

// ---------------- scratch (static zero-init; replay-safe) -------------------
__device__ int                g_hist[NBIN];
__device__ int                g_scal[8];   // 4:n_act 5:n_stages
__device__ int                g_sel[TOP_M];
__device__ int                g_boundary[N_STM];
__device__ float              g_Kproj[TOP_M*64];
__device__ float              g_kpN[TOP_M*64];
__device__ __align__(16) __nv_bfloat16 g_kpB[TOP_M*64];
__device__ float              g_omega[TOP_M];
__device__ float              g_lknC[(size_t)(N_LTM+128)*64];
__device__ __align__(16) __nv_bfloat16 g_lknB[(size_t)(N_LTM+128)*64];
__device__ unsigned           g_ajinv[N_LTM+128];
__device__ float              g_smax[(size_t)TOP_M*NSMAX];
__device__ unsigned           g_gmaxU[TOP_M];
__device__ unsigned long long g_key[TOP_M];
__device__ int                g_unm[TOP_M];
__device__ int                g_rank[TOP_M];
__device__ int                g_free[TOP_M];

// ---------------- helpers ---------------------------------------------------
__device__ __forceinline__ unsigned fmono(float f) {
    unsigned u = __float_as_uint(f);
    return (u & 0x80000000u) ? ~u : (u | 0x80000000u);
}
__device__ __forceinline__ float funmono(unsigned m) {
    unsigned u = (m & 0x80000000u) ? (m ^ 0x80000000u) : ~m;
    return __uint_as_float(u);
}
__device__ __forceinline__ unsigned long long stm_key(int i, float h) {
    return ((unsigned long long)__float_as_uint(h) << 32) | (0xFFFFFFFFu - (unsigned)i);
}
__device__ __forceinline__ int hbin(float h) {
    return min(max((int)(h * (float)NBIN), 0), NBIN - 1);
}
__device__ __forceinline__ void gw(float* w, float& inv) {
    w[0] = 1.0f; float sum = 1.0f;
    #pragma unroll
    for (int i = 1; i < 7; ++i) {
        w[i] = expf(-0.5f * (float)(i * i) / 4.0f);
        sum += 2.0f * w[i];
    }
    inv = 1.0f / sum;
}
__device__ __forceinline__ void mma16816(float* c, const unsigned* a, const unsigned* b) {
    asm volatile("mma.sync.aligned.m16n8k16.row.col.f32.bf16.bf16.f32 "
                 "{%0,%1,%2,%3}, {%4,%5,%6,%7}, {%8,%9}, {%0,%1,%2,%3};"
                 : "+f"(c[0]), "+f"(c[1]), "+f"(c[2]), "+f"(c[3])
                 : "r"(a[0]), "r"(a[1]), "r"(a[2]), "r"(a[3]), "r"(b[0]), "r"(b[1]));
}
// k-pair permutation: (x, x+4) u32 cols adjacent within each 8-col chunk
__device__ __forceinline__ int kperm(int cu) {
    return (cu & ~7) + ((cu & 3) * 2 + ((cu >> 2) & 1));
}

// ---- side: base-state copy (ltm->out head) + stm_V norm clip ---------------
__global__ void k_side(const float4* __restrict__ K, const float4* __restrict__ V,
                       const float4* __restrict__ e, const float4* __restrict__ h,
                       float4* __restrict__ out,
                       const float* __restrict__ stm_V, float* __restrict__ oSV) {
    if (blockIdx.x < 12608) {
        int i = blockIdx.x * blockDim.x + threadIdx.x;   // 3227648 total
        float4 v;
        if (i < 1048576)       v = K[i];
        else if (i < 3145728)  v = V[i - 1048576];
        else if (i < 3211264)  v = e[i - 3145728];
        else                   v = h[i - 3211264];
        out[i] = v;
    } else {
        int b = blockIdx.x - 12608;                      // 8192 blocks
        int w = threadIdx.x >> 5, lane = threadIdx.x & 31;
        size_t row = (size_t)b * 8 + w;
        float4 v = reinterpret_cast<const float4*>(stm_V)[row * 32 + lane];
        float sq = v.x*v.x + v.y*v.y + v.z*v.z + v.w*v.w;
        #pragma unroll
        for (int off = 16; off; off >>= 1) sq += __shfl_xor_sync(0xFFFFFFFFu, sq, off);
        float sc = fminf(1.0f, 2.0f / (sqrtf(sq) + 1e-8f));
        reinterpret_cast<float4*>(oSV)[row * 32 + lane] =
            make_float4(v.x*sc, v.y*sc, v.z*sc, v.w*sc);
    }
}

// ---- 1: ltm_K normalize + active compaction (fp32 + bf16) | stm histogram --
__global__ void k_histlkn(const float* __restrict__ ltm_K, const int* __restrict__ ltm_act,
                          const float* __restrict__ stm_h, const int* __restrict__ stm_act) {
    __shared__ float part[8];
    __shared__ int sact[4];
    __shared__ int sbase;
    int tid = threadIdx.x;
    int g = tid >> 6, c = tid & 63, wid = tid >> 5, lane = tid & 31;
    int j = blockIdx.x * 4 + g;
    float v = ltm_K[(size_t)j * 64 + c];
    float sq = v * v;
    #pragma unroll
    for (int off = 16; off; off >>= 1) sq += __shfl_xor_sync(0xFFFFFFFFu, sq, off);
    if (lane == 0) part[wid] = sq;
    int a = (ltm_act[j] > 0) ? 1 : 0;
    if (c == 0) sact[g] = a;
    __syncthreads();
    if (tid == 0) {
        int tot = sact[0] + sact[1] + sact[2] + sact[3];
        sbase = tot ? atomicAdd(&g_scal[4], tot) : 0;
    }
    __syncthreads();
    if (a) {
        int off = 0;
        #pragma unroll
        for (int x = 0; x < 4; ++x) if (x < g) off += sact[x];
        int pos = sbase + off;
        float tot = part[g * 2] + part[g * 2 + 1];
        float nv = v / (sqrtf(tot) + 1e-8f);
        g_lknC[(size_t)pos * 64 + c] = nv;
        g_lknB[(size_t)pos * 64 + c] = __float2bfloat16(nv);
        if (c == 0) g_ajinv[pos] = 0xFFFFFFFFu - (unsigned)j;
    }
    int i = blockIdx.x * 256 + tid;
    if (i < N_STM && stm_act[i] > 0) atomicAdd(&g_hist[hbin(stm_h[i])], 1);
}

// ---- 2: block 0 = threshold+pad+compaction+tie-break; block 1 = freeslots --
__global__ void k_prep(const float* __restrict__ fat, float* __restrict__ oF,
                       const float* __restrict__ h, const int* __restrict__ act,
                       const int* __restrict__ ltm_act) {
    int t = threadIdx.x;
    if (blockIdx.x == 1) {
        int w = t >> 5, lane = t & 31;
        __shared__ int wcnt[32];
        int running = 0;
        for (int tile = 0; tile < 64 && running < TOP_M; ++tile) {
            int i = tile * 1024 + t;
            int inact = (ltm_act[i] == 0);
            unsigned bal = __ballot_sync(0xFFFFFFFFu, inact);
            if (lane == 0) wcnt[w] = __popc(bal);
            __syncthreads();
            int pre = 0, total = 0;
            #pragma unroll
            for (int x = 0; x < 32; ++x) {
                int cx = wcnt[x];
                if (x < w) pre += cx;
                total += cx;
            }
            int pos = running + pre + __popc(bal & ((1u << lane) - 1));
            if (inact && pos < TOP_M) g_free[pos] = i;
            running += total;
            __syncthreads();
        }
        return;
    }
    __shared__ int s[1024];
    __shared__ int sT, sCnt, ssel, sbnd;
    int base = NBIN - 1 - 4 * t;
    int h0 = g_hist[base], h1 = g_hist[base-1], h2 = g_hist[base-2], h3 = g_hist[base-3];
    g_hist[base] = 0; g_hist[base-1] = 0; g_hist[base-2] = 0; g_hist[base-3] = 0;
    int sum = h0 + h1 + h2 + h3;
    s[t] = sum;
    if (t == 0) { ssel = 0; sbnd = 0; }
    __syncthreads();
    for (int off = 1; off < 1024; off <<= 1) {
        int v = s[t], a2 = (t >= off) ? s[t - off] : 0;
        __syncthreads(); s[t] = v + a2; __syncthreads();
    }
    int c = s[t] - sum;
    int hh[4] = {h0, h1, h2, h3};
    #pragma unroll
    for (int q = 0; q < 4; ++q) {
        if (c < TOP_M && c + hh[q] >= TOP_M) { sT = base - q; sCnt = c; }
        c += hh[q];
    }
    int n_act = g_scal[4];
    for (int idx = t; idx < 128 * 64; idx += 1024) {
        g_lknC[(size_t)n_act * 64 + idx] = 0.0f;
        g_lknB[(size_t)n_act * 64 + idx] = __float2bfloat16(0.0f);
    }
    if (t < 128) g_ajinv[n_act + t] = 0u;
    if (t == 0) {
        g_scal[5] = (n_act + 127) >> 7;
        oF[0] = 0.2f * fat[0];
    }
    __syncthreads();
    int T = sT;
    for (int b2 = 0; b2 < N_STM; b2 += 4096) {
        int ia[4]; float ha[4];
        #pragma unroll
        for (int q = 0; q < 4; ++q) {
            int i = b2 + q * 1024 + t;
            ia[q] = act[i]; ha[q] = h[i];
        }
        #pragma unroll
        for (int q = 0; q < 4; ++q) {
            if (ia[q] > 0) {
                int bn = hbin(ha[q]);
                int i = b2 + q * 1024 + t;
                if (bn > T)       g_sel[atomicAdd(&ssel, 1)] = i;
                else if (bn == T) g_boundary[atomicAdd(&sbnd, 1)] = i;
            }
        }
    }
    __syncthreads();
    int B = sbnd, need = TOP_M - sCnt;
    for (int cc = t; cc < B; cc += 1024) {
        int i = g_boundary[cc];
        unsigned long long k = stm_key(i, h[i]);
        int r = 0;
        for (int q = 0; q < B; ++q) {
            int i2 = g_boundary[q];
            r += (stm_key(i2, h[i2]) > k);
        }
        if (r < need) g_sel[atomicAdd(&ssel, 1)] = i;
    }
    __syncthreads();
    if (t == 0) g_scal[4] = 0;   // restore for graph replay
}

// ---- 3: projection + kp normalize (fp32 + bf16) ----------------------------
__global__ void k_proj(const float* __restrict__ stm_K, const float* __restrict__ stm_h,
                       const float* __restrict__ W, const float* __restrict__ b) {
    int m = blockIdx.x, c = threadIdx.x;
    __shared__ float sK[16];
    __shared__ float ws[2];
    int s = g_sel[m];
    if (c < 16) sK[c] = stm_K[(size_t)s * 16 + c];
    __syncthreads();
    float acc = b[c];
    #pragma unroll
    for (int k = 0; k < 16; ++k) acc = fmaf(sK[k], W[k * 64 + c], acc);
    float sq = acc * acc;
    #pragma unroll
    for (int off = 16; off; off >>= 1) sq += __shfl_xor_sync(0xFFFFFFFFu, sq, off);
    if ((c & 31) == 0) ws[c >> 5] = sq;
    __syncthreads();
    float kpv = acc / (sqrtf(ws[0] + ws[1]) + 1e-8f);
    g_Kproj[m * 64 + c] = acc;
    g_kpN[m * 64 + c] = kpv;
    g_kpB[m * 64 + c] = __float2bfloat16(kpv);
    if (c == 0) g_omega[m] = 0.05f * stm_h[s];
}

// ---- 4 (S1): bf16 HMMA screen, CTA 128m x 128j (halved B traffic) ----------
__global__ void __launch_bounds__(256) k_simsT() {
    __shared__ __align__(16) unsigned sA32[128 * 40];
    __shared__ __align__(16) unsigned sB32[128 * 40];
    __shared__ unsigned s_max[128];
    const int tid = threadIdx.x, wid = tid >> 5, l = tid & 31;
    const int warp_m = wid >> 2, warp_n = wid & 3;   // warp_m in {0,1} -> 64 rows each
    const int m0 = blockIdx.x * 128;
    const int ns = g_scal[5];

    {   // A fill: 128 rows x 32 u32, permuted
        const unsigned* src = (const unsigned*)(g_kpB + (size_t)m0 * 64);
        #pragma unroll
        for (int i = 0; i < 16; ++i) {
            int idx = tid + i * 256;
            int row = idx >> 5, cu = idx & 31;
            sA32[row * 40 + kperm(cu)] = src[idx];
        }
    }

    float runmax = -3.0f;

    for (int t = blockIdx.y; t < ns; t += (int)gridDim.y) {
        __syncthreads();
        {
            const unsigned* src = (const unsigned*)(g_lknB + (size_t)t * 128 * 64);
            #pragma unroll
            for (int i = 0; i < 16; ++i) {
                int idx = tid + i * 256;
                int row = idx >> 5, cu = idx & 31;
                sB32[row * 40 + kperm(cu)] = __ldg(&src[idx]);
            }
        }
        if (tid < 128) s_max[tid] = 0u;
        __syncthreads();

        float acc[4][4][4];
        #pragma unroll
        for (int i = 0; i < 4; ++i)
            #pragma unroll
            for (int q = 0; q < 4; ++q)
                #pragma unroll
                for (int r = 0; r < 4; ++r) acc[i][q][r] = 0.0f;

        #pragma unroll
        for (int ch = 0; ch < 4; ++ch) {
            unsigned a[4][4], b[4][2];
            int cb = ch * 8 + (l & 3) * 2;
            #pragma unroll
            for (int i = 0; i < 4; ++i) {
                int r0 = warp_m * 64 + i * 16 + (l >> 2);
                unsigned long long v0 =
                    *reinterpret_cast<const unsigned long long*>(&sA32[r0 * 40 + cb]);
                unsigned long long v1 =
                    *reinterpret_cast<const unsigned long long*>(&sA32[(r0 + 8) * 40 + cb]);
                a[i][0] = (unsigned)v0; a[i][2] = (unsigned)(v0 >> 32);
                a[i][1] = (unsigned)v1; a[i][3] = (unsigned)(v1 >> 32);
            }
            #pragma unroll
            for (int q = 0; q < 4; ++q) {
                int rb = warp_n * 32 + q * 8 + (l >> 2);
                unsigned long long v =
                    *reinterpret_cast<const unsigned long long*>(&sB32[rb * 40 + cb]);
                b[q][0] = (unsigned)v; b[q][1] = (unsigned)(v >> 32);
            }
            #pragma unroll
            for (int i = 0; i < 4; ++i)
                #pragma unroll
                for (int q = 0; q < 4; ++q)
                    mma16816(acc[i][q], a[i], b[q]);
        }

        #pragma unroll
        for (int i = 0; i < 4; ++i) {
            float t0 = -3.0f, t1 = -3.0f;
            #pragma unroll
            for (int q = 0; q < 4; ++q) {
                t0 = fmaxf(t0, fmaxf(acc[i][q][0], acc[i][q][1]));
                t1 = fmaxf(t1, fmaxf(acc[i][q][2], acc[i][q][3]));
            }
            t0 = fmaxf(t0, __shfl_xor_sync(0xFFFFFFFFu, t0, 1));
            t0 = fmaxf(t0, __shfl_xor_sync(0xFFFFFFFFu, t0, 2));
            t1 = fmaxf(t1, __shfl_xor_sync(0xFFFFFFFFu, t1, 1));
            t1 = fmaxf(t1, __shfl_xor_sync(0xFFFFFFFFu, t1, 2));
            if ((l & 3) == 0) {
                int r0 = warp_m * 64 + i * 16 + (l >> 2);
                atomicMax(&s_max[r0], fmono(t0));
                atomicMax(&s_max[r0 + 8], fmono(t1));
            }
        }
        __syncthreads();
        if (tid < 128) {
            float v = funmono(s_max[tid]);
            g_smax[(size_t)(m0 + tid) * NSMAX + t] = v;
            runmax = fmaxf(runmax, v);
        }
    }
    if (tid < 128) atomicMax(&g_gmaxU[m0 + tid], fmono(runmax));
}

// ---- 5 (S2): exact fp32 recheck + fused matched scatter --------------------
// Band 0.01 >= 2x the provable bf16 bound (2*0.004): true argmax guaranteed
// rechecked; exact values decide matched/argmax, bit-compatible with fp32 ref.
__global__ void k_exmat(const float* __restrict__ stm_V, const float* __restrict__ stm_e,
                        const float* __restrict__ stm_h,
                        float* __restrict__ oK, float* __restrict__ oV,
                        float* __restrict__ oe, float* __restrict__ oh) {
    int wid = threadIdx.x >> 5, lane = threadIdx.x & 31;
    int m = blockIdx.x * 8 + wid;
    int ns = g_scal[5];
    float thr = funmono(g_gmaxU[m]) - 0.01f;
    float4 kp4[16];
    const float4* kpr = reinterpret_cast<const float4*>(g_kpN + m * 64);
    #pragma unroll
    for (int i = 0; i < 16; ++i) kp4[i] = kpr[i];
    unsigned long long best = 0ull;
    for (int t = 0; t < ns; ++t) {
        if (g_smax[(size_t)m * NSMAX + t] < thr) continue;
        #pragma unroll
        for (int q = 0; q < 4; ++q) {
            int j = t * 128 + lane + q * 32;
            const float4* br = reinterpret_cast<const float4*>(g_lknC + (size_t)j * 64);
            float dot = 0.f;
            #pragma unroll
            for (int i = 0; i < 16; ++i) {
                float4 b4 = br[i];
                dot = fmaf(kp4[i].x, b4.x, dot);
                dot = fmaf(kp4[i].y, b4.y, dot);
                dot = fmaf(kp4[i].z, b4.z, dot);
                dot = fmaf(kp4[i].w, b4.w, dot);
            }
            unsigned long long pk =
                ((unsigned long long)fmono(dot) << 32) | g_ajinv[j];
            if (pk > best) best = pk;
        }
    }
    #pragma unroll
    for (int off = 16; off; off >>= 1) {
        unsigned long long o = __shfl_xor_sync(0xFFFFFFFFu, best, off);
        if (o > best) best = o;
    }
    // fused matched scatter (warp-parallel; keeps 2048-warp parallelism)
    float sim = funmono((unsigned)(best >> 32));
    int j = (int)(0xFFFFFFFFu - (unsigned)(best & 0xFFFFFFFFull));
    bool matched = (sim >= 0.5f);
    int s = g_sel[m];
    float om = g_omega[m];
    if (lane == 0) {
        g_unm[m] = matched ? 0 : 1;
        g_key[m] = stm_key(s, stm_h[s]);
        g_gmaxU[m] = 0u;   // reset for graph replay
        if (matched) atomicAdd(&oh[j], om);
    }
    if (matched) {
        #pragma unroll
        for (int q = 0; q < 2; ++q) {
            int c = lane + q * 32;
            atomicAdd(&oK[(size_t)j * 64 + c], om * g_Kproj[m * 64 + c]);
        }
        #pragma unroll
        for (int q = 0; q < 4; ++q) {
            int c = lane + q * 32;
            atomicAdd(&oV[(size_t)j * 128 + c], om * stm_V[(size_t)s * 128 + c]);
        }
        if (lane < 4) atomicAdd(&oe[(size_t)j * 4 + lane], om * stm_e[(size_t)s * 4 + lane]);
    }
}

// ---- 6: rank unmatched (h desc, idx asc) -------------------------------------
__global__ void k_rank() {
    __shared__ unsigned long long sk[TOP_M];
    __shared__ unsigned char su[TOP_M];
    int t = threadIdx.x;
    for (int i = t; i < TOP_M; i += 256) { sk[i] = g_key[i]; su[i] = (unsigned char)g_unm[i]; }
    __syncthreads();
    int m = blockIdx.x * 256 + t;
    if (g_unm[m]) {
        unsigned long long k = sk[m];
        int r = 0;
        for (int i = 0; i < TOP_M; ++i) r += (su[i] && sk[i] > k);
        g_rank[m] = r;
    }
}

// ---- 7: unmatched fresh-slot writes (2048-way parallel) ----------------------
__global__ void k_unmatch(const float* __restrict__ stm_V, const float* __restrict__ stm_e,
                          float* __restrict__ oK, float* __restrict__ oV,
                          float* __restrict__ oe, float* __restrict__ oh) {
    int m = blockIdx.x;
    if (!g_unm[m]) return;
    int slot = g_free[g_rank[m]], c = threadIdx.x, s = g_sel[m];
    oK[(size_t)slot * 64 + c] = g_Kproj[m * 64 + c];
    oV[(size_t)slot * 128 + c] = stm_V[(size_t)s * 128 + c];
    oV[(size_t)slot * 128 + 64 + c] = stm_V[(size_t)s * 128 + 64 + c];
    if (c < 4) oe[(size_t)slot * 4 + c] = stm_e[(size_t)s * 4 + c];
    if (c == 0) oh[slot] = g_omega[m];
}

// ---- fused 3D gaussian blur + merge (branchless, div-free) -------------------
#define BLUR_SMEM ((10368 + 10368) * 4)   // 82944 B
__global__ void __launch_bounds__(256) k_blurAll(const float* __restrict__ stm_t,
                                                 const float* __restrict__ ltm_t,
                                                 float* __restrict__ oT) {
    extern __shared__ float p[];
    float* p0 = p;
    float* p0c = p + 576;
    float* p1 = p + 10368;
    float w[7], inv; gw(w, inv);
    int tid = threadIdx.x;
    int plane = blockIdx.x;
    int c = plane / 96, d = plane % 96;
    size_t cbase = (size_t)c * 96 * 9216;

    for (int i = tid; i < 576; i += 256) { p0[i] = 0.0f; p0[9792 + i] = 0.0f; }
    for (int i = tid; i < 1152; i += 256) {
        int row = i / 12, cc = i - row * 12;
        p1[row * 108 + (cc < 6 ? cc : 96 + cc)] = 0.0f;
    }

    float4 acc[9];
    #pragma unroll
    for (int e = 0; e < 9; ++e) acc[e] = make_float4(0.f, 0.f, 0.f, 0.f);
    #pragma unroll
    for (int t = -6; t <= 6; ++t) {
        int dd = d + t;
        if (dd < 0 || dd >= 96) continue;
        float ww = w[t < 0 ? -t : t];
        const float4* src = reinterpret_cast<const float4*>(stm_t + cbase + (size_t)dd * 9216);
        #pragma unroll
        for (int e = 0; e < 9; ++e) {
            float4 v = src[tid + e * 256];
            acc[e].x = fmaf(v.x, ww, acc[e].x);
            acc[e].y = fmaf(v.y, ww, acc[e].y);
            acc[e].z = fmaf(v.z, ww, acc[e].z);
            acc[e].w = fmaf(v.w, ww, acc[e].w);
        }
    }
    float4* d0 = reinterpret_cast<float4*>(p0c);
    #pragma unroll
    for (int e = 0; e < 9; ++e) {
        float4 v = acc[e];
        d0[tid + e * 256] = make_float4(v.x * inv, v.y * inv, v.z * inv, v.w * inv);
    }
    __syncthreads();

    {
        int h = tid / 96;
        int x = tid - h * 96;
        for (int i = tid; i < 9216; i += 256) {
            float a2 = p0c[i] * w[0];
            #pragma unroll
            for (int t = 1; t < 7; ++t)
                a2 += (p0c[i - t * 96] + p0c[i + t * 96]) * w[t];
            p1[h * 108 + 6 + x] = a2 * inv;
            x += 64; h += 2;
            if (x >= 96) { x -= 96; h += 1; }
        }
    }
    __syncthreads();

    {
        float xi = (c == 0) ? 0.005f : 0.003f;
        size_t base = cbase + (size_t)d * 9216;
        int h = tid / 96;
        int x = tid - h * 96;
        for (int i = tid; i < 9216; i += 256) {
            const float* row = p1 + h * 108 + 6 + x;
            float a2 = row[0] * w[0];
            #pragma unroll
            for (int t = 1; t < 7; ++t)
                a2 += (row[-t] + row[t]) * w[t];
            oT[base + i] = ltm_t[base + i] + xi * (a2 * inv);
            x += 64; h += 2;
            if (x >= 96) { x -= 96; h += 1; }
        }
    }
}

extern "C" void kernel_launch(void* const* d_in, const int* in_sizes, int n_in,
                              void* d_out, int out_size) {
    (void)in_sizes; (void)n_in; (void)out_size;
    const float* stm_K   = (const float*)d_in[0];
    const float* stm_V   = (const float*)d_in[1];
    const float* stm_e   = (const float*)d_in[2];
    const float* stm_h   = (const float*)d_in[3];
    const float* ltm_K   = (const float*)d_in[4];
    const float* ltm_V   = (const float*)d_in[5];
    const float* ltm_e   = (const float*)d_in[6];
    const float* ltm_h   = (const float*)d_in[7];
    const float* W       = (const float*)d_in[8];
    const float* b       = (const float*)d_in[9];
    const float* stm_t   = (const float*)d_in[10];
    const float* ltm_t   = (const float*)d_in[11];
    const float* fatigue = (const float*)d_in[12];
    const int*   stm_act = (const int*)d_in[13];
    const int*   ltm_act = (const int*)d_in[14];

    float* out = (float*)d_out;
    float* oK  = out;                 // 65536*64
    float* oV  = out + 4194304;       // 65536*128
    float* oe  = out + 12582912;      // 65536*4
    float* oh  = out + 12845056;      // 65536
    float* oSV = out + 12910592;      // 65536*128
    float* oT  = out + 21299200;      // 5*96^3
    float* oF  = out + 25722880;      // 1

    static cudaStream_t sB = 0, sD = 0;
    static cudaEvent_t eR = 0, eB = 0, eD = 0;
    static bool init_done = false;
    if (!init_done) {
        cudaFuncSetAttribute(k_blurAll, cudaFuncAttributeMaxDynamicSharedMemorySize, BLUR_SMEM);
        cudaStreamCreateWithFlags(&sB, cudaStreamNonBlocking);
        cudaStreamCreateWithFlags(&sD, cudaStreamNonBlocking);
        cudaEventCreateWithFlags(&eR, cudaEventDisableTiming);
        cudaEventCreateWithFlags(&eB, cudaEventDisableTiming);
        cudaEventCreateWithFlags(&eD, cudaEventDisableTiming);
        init_done = true;
    }

    // fork
    cudaEventRecord(eR, 0);
    cudaStreamWaitEvent(sB, eR, 0);
    cudaStreamWaitEvent(sD, eR, 0);

    // critical path first (k_simsT = launch #4 for ncu)
    k_histlkn<<<16384, 256>>>(ltm_K, ltm_act, stm_h, stm_act);
    k_prep<<<2, 1024>>>(fatigue, oF, stm_h, stm_act, ltm_act);
    k_proj<<<2048, 64>>>(stm_K, stm_h, W, b);
    k_simsT<<<dim3(16, 18), 256>>>();

    // side chain B: base copy + stm_V clip (one kernel)
    k_side<<<20800, 256, 0, sB>>>((const float4*)ltm_K, (const float4*)ltm_V,
                                  (const float4*)ltm_e, (const float4*)ltm_h,
                                  (float4*)oK, stm_V, oSV);
    cudaEventRecord(eB, sB);

    // side chain D: fused terrain blur + merge
    k_blurAll<<<480, 256, BLUR_SMEM, sD>>>(stm_t, ltm_t, oT);
    cudaEventRecord(eD, sD);

    // tail of critical path (exmat writes into copied base state)
    cudaStreamWaitEvent(0, eB, 0);
    k_exmat<<<256, 256>>>(stm_V, stm_e, stm_h, oK, oV, oe, oh);
    k_rank<<<8, 256>>>();
    k_unmatch<<<2048, 64>>>(stm_V, stm_e, oK, oV, oe, oh);

    // join remaining side chain
    cudaStreamWaitEvent(0, eD, 0);
}

// round 15
// speedup vs baseline: 1.7593x; 1.0629x over previous
#include <cuda_runtime.h>
#include <cuda_bf16.h>
#include <cstdint>
#include <math.h>

#define N_STM 65536
#define N_LTM 65536
#define TOP_M 2048
#define NBIN  4096
#define TVOL  (5*96*96*96)
#define NSMAX 516

// ---------------- scratch (static zero-init; replay-safe) -------------------
__device__ int                g_hist[NBIN];
__device__ int                g_scal[8];   // 0:T 1:cnt_above 2:sel_ctr 3:bnd_ctr 4:n_act 5:n_stages 6:done
__device__ int                g_sel[TOP_M];
__device__ int                g_boundary[N_STM];
__device__ float              g_Kproj[TOP_M*64];
__device__ float              g_kpN[TOP_M*64];
__device__ __align__(16) __nv_bfloat16 g_kpB[TOP_M*64];
__device__ float              g_omega[TOP_M];
__device__ float              g_lknC[(size_t)(N_LTM+128)*64];
__device__ __align__(16) __nv_bfloat16 g_lknB[(size_t)(N_LTM+128)*64];
__device__ unsigned           g_ajinv[N_LTM+128];
__device__ float              g_smax[(size_t)TOP_M*NSMAX];
__device__ unsigned           g_gmaxU[TOP_M];
__device__ unsigned long long g_key[TOP_M];
__device__ int                g_unm[TOP_M];
__device__ int                g_rank[TOP_M];
__device__ int                g_free[TOP_M];

// ---------------- helpers ---------------------------------------------------
__device__ __forceinline__ unsigned fmono(float f) {
    unsigned u = __float_as_uint(f);
    return (u & 0x80000000u) ? ~u : (u | 0x80000000u);
}
__device__ __forceinline__ float funmono(unsigned m) {
    unsigned u = (m & 0x80000000u) ? (m ^ 0x80000000u) : ~m;
    return __uint_as_float(u);
}
__device__ __forceinline__ unsigned long long stm_key(int i, float h) {
    return ((unsigned long long)__float_as_uint(h) << 32) | (0xFFFFFFFFu - (unsigned)i);
}
__device__ __forceinline__ int hbin(float h) {
    return min(max((int)(h * (float)NBIN), 0), NBIN - 1);
}
__device__ __forceinline__ void gw(float* w, float& inv) {
    w[0] = 1.0f; float sum = 1.0f;
    #pragma unroll
    for (int i = 1; i < 7; ++i) {
        w[i] = expf(-0.5f * (float)(i * i) / 4.0f);
        sum += 2.0f * w[i];
    }
    inv = 1.0f / sum;
}
__device__ __forceinline__ void mma16816(float* c, const unsigned* a, const unsigned* b) {
    asm volatile("mma.sync.aligned.m16n8k16.row.col.f32.bf16.bf16.f32 "
                 "{%0,%1,%2,%3}, {%4,%5,%6,%7}, {%8,%9}, {%0,%1,%2,%3};"
                 : "+f"(c[0]), "+f"(c[1]), "+f"(c[2]), "+f"(c[3])
                 : "r"(a[0]), "r"(a[1]), "r"(a[2]), "r"(a[3]), "r"(b[0]), "r"(b[1]));
}
// k-pair permutation: (x, x+4) u32 cols adjacent within each 8-col chunk
__device__ __forceinline__ int kperm(int cu) {
    return (cu & ~7) + ((cu & 3) * 2 + ((cu >> 2) & 1));
}

// ---- base-state copy: ltm {K,V,e,h} -> contiguous head of d_out ------------
__global__ void k_copy(const float4* __restrict__ K, const float4* __restrict__ V,
                       const float4* __restrict__ e, const float4* __restrict__ h,
                       float4* __restrict__ out) {
    int i = blockIdx.x * blockDim.x + threadIdx.x;   // 3227648 total
    float4 v;
    if (i < 1048576)       v = K[i];
    else if (i < 3145728)  v = V[i - 1048576];
    else if (i < 3211264)  v = e[i - 3145728];
    else                   v = h[i - 3211264];
    out[i] = v;
}

// ---- stm_V norm clip --------------------------------------------------------
__global__ void k_stmv(const float* __restrict__ stm_V, float* __restrict__ oSV) {
    int w = threadIdx.x >> 5, lane = threadIdx.x & 31;
    size_t row = (size_t)blockIdx.x * 8 + w;
    float4 v = reinterpret_cast<const float4*>(stm_V)[row * 32 + lane];
    float sq = v.x*v.x + v.y*v.y + v.z*v.z + v.w*v.w;
    #pragma unroll
    for (int off = 16; off; off >>= 1) sq += __shfl_xor_sync(0xFFFFFFFFu, sq, off);
    float sc = fminf(1.0f, 2.0f / (sqrtf(sq) + 1e-8f));
    reinterpret_cast<float4*>(oSV)[row * 32 + lane] =
        make_float4(v.x*sc, v.y*sc, v.z*sc, v.w*sc);
}

// ---- 1: ltm_K normalize + active compaction (fp32 + bf16) | stm histogram --
__global__ void k_histlkn(const float* __restrict__ ltm_K, const int* __restrict__ ltm_act,
                          const float* __restrict__ stm_h, const int* __restrict__ stm_act) {
    __shared__ float part[8];
    __shared__ int sact[4];
    __shared__ int sbase;
    int tid = threadIdx.x;
    int g = tid >> 6, c = tid & 63, wid = tid >> 5, lane = tid & 31;
    int j = blockIdx.x * 4 + g;
    float v = ltm_K[(size_t)j * 64 + c];
    float sq = v * v;
    #pragma unroll
    for (int off = 16; off; off >>= 1) sq += __shfl_xor_sync(0xFFFFFFFFu, sq, off);
    if (lane == 0) part[wid] = sq;
    int a = (ltm_act[j] > 0) ? 1 : 0;
    if (c == 0) sact[g] = a;
    __syncthreads();
    if (tid == 0) {
        int tot = sact[0] + sact[1] + sact[2] + sact[3];
        sbase = tot ? atomicAdd(&g_scal[4], tot) : 0;
    }
    __syncthreads();
    if (a) {
        int off = 0;
        #pragma unroll
        for (int x = 0; x < 4; ++x) if (x < g) off += sact[x];
        int pos = sbase + off;
        float tot = part[g * 2] + part[g * 2 + 1];
        float nv = v / (sqrtf(tot) + 1e-8f);
        g_lknC[(size_t)pos * 64 + c] = nv;
        g_lknB[(size_t)pos * 64 + c] = __float2bfloat16(nv);
        if (c == 0) g_ajinv[pos] = 0xFFFFFFFFu - (unsigned)j;
    }
    int i = blockIdx.x * 256 + tid;
    if (i < N_STM && stm_act[i] > 0) atomicAdd(&g_hist[hbin(stm_h[i])], 1);
}

// ---- 2: block 0 = threshold + pad; block 1 = freeslots ---------------------
__global__ void k_prep(const float* __restrict__ fat, float* __restrict__ oF,
                       const int* __restrict__ ltm_act) {
    int t = threadIdx.x;
    if (blockIdx.x == 1) {
        int w = t >> 5, lane = t & 31;
        __shared__ int wcnt[32];
        int running = 0;
        for (int tile = 0; tile < 64 && running < TOP_M; ++tile) {
            int i = tile * 1024 + t;
            int inact = (ltm_act[i] == 0);
            unsigned bal = __ballot_sync(0xFFFFFFFFu, inact);
            if (lane == 0) wcnt[w] = __popc(bal);
            __syncthreads();
            int pre = 0, total = 0;
            #pragma unroll
            for (int x = 0; x < 32; ++x) {
                int cx = wcnt[x];
                if (x < w) pre += cx;
                total += cx;
            }
            int pos = running + pre + __popc(bal & ((1u << lane) - 1));
            if (inact && pos < TOP_M) g_free[pos] = i;
            running += total;
            __syncthreads();
        }
        return;
    }
    __shared__ int s[1024];
    int base = NBIN - 1 - 4 * t;
    int h0 = g_hist[base], h1 = g_hist[base-1], h2 = g_hist[base-2], h3 = g_hist[base-3];
    g_hist[base] = 0; g_hist[base-1] = 0; g_hist[base-2] = 0; g_hist[base-3] = 0;
    int sum = h0 + h1 + h2 + h3;
    s[t] = sum;
    __syncthreads();
    for (int off = 1; off < 1024; off <<= 1) {
        int v = s[t], a2 = (t >= off) ? s[t - off] : 0;
        __syncthreads(); s[t] = v + a2; __syncthreads();
    }
    int c = s[t] - sum;
    int hh[4] = {h0, h1, h2, h3};
    #pragma unroll
    for (int q = 0; q < 4; ++q) {
        if (c < TOP_M && c + hh[q] >= TOP_M) { g_scal[0] = base - q; g_scal[1] = c; }
        c += hh[q];
    }
    int n_act = g_scal[4];
    for (int idx = t; idx < 128 * 64; idx += 1024) {
        g_lknC[(size_t)n_act * 64 + idx] = 0.0f;
        g_lknB[(size_t)n_act * 64 + idx] = __float2bfloat16(0.0f);
    }
    if (t < 128) g_ajinv[n_act + t] = 0u;
    if (t == 0) {
        g_scal[5] = (n_act + 127) >> 7;
        g_scal[4] = 0;   // restore for replay
        oF[0] = 0.2f * fat[0];
    }
}

// ---- 2b: grid-parallel top-M classification + last-block tie-break ---------
__global__ void k_compact(const float* __restrict__ h, const int* __restrict__ act) {
    __shared__ int sdone;
    int t = threadIdx.x;
    int i = blockIdx.x * 1024 + t;
    int T = g_scal[0];
    if (act[i] > 0) {
        int bn = hbin(h[i]);
        if (bn > T)       g_sel[atomicAdd(&g_scal[2], 1)] = i;
        else if (bn == T) g_boundary[atomicAdd(&g_scal[3], 1)] = i;
    }
    __threadfence();
    __syncthreads();
    if (t == 0) sdone = atomicAdd(&g_scal[6], 1);
    __syncthreads();
    if (sdone == 63) {   // last block: boundary tie-break (h desc, idx asc)
        int B = g_scal[3], need = TOP_M - g_scal[1];
        for (int cc = t; cc < B; cc += 1024) {
            int ii = g_boundary[cc];
            unsigned long long k = stm_key(ii, h[ii]);
            int r = 0;
            for (int q = 0; q < B; ++q) {
                int i2 = g_boundary[q];
                r += (stm_key(i2, h[i2]) > k);
            }
            if (r < need) g_sel[atomicAdd(&g_scal[2], 1)] = ii;
        }
        __syncthreads();
        if (t == 0) { g_scal[2] = 0; g_scal[3] = 0; g_scal[6] = 0; }  // replay reset
    }
}

// ---- 3: projection + kp normalize (fp32 + bf16) ----------------------------
__global__ void k_proj(const float* __restrict__ stm_K, const float* __restrict__ stm_h,
                       const float* __restrict__ W, const float* __restrict__ b) {
    int m = blockIdx.x, c = threadIdx.x;
    __shared__ float sK[16];
    __shared__ float ws[2];
    int s = g_sel[m];
    if (c < 16) sK[c] = stm_K[(size_t)s * 16 + c];
    __syncthreads();
    float acc = b[c];
    #pragma unroll
    for (int k = 0; k < 16; ++k) acc = fmaf(sK[k], W[k * 64 + c], acc);
    float sq = acc * acc;
    #pragma unroll
    for (int off = 16; off; off >>= 1) sq += __shfl_xor_sync(0xFFFFFFFFu, sq, off);
    if ((c & 31) == 0) ws[c >> 5] = sq;
    __syncthreads();
    float kpv = acc / (sqrtf(ws[0] + ws[1]) + 1e-8f);
    g_Kproj[m * 64 + c] = acc;
    g_kpN[m * 64 + c] = kpv;
    g_kpB[m * 64 + c] = __float2bfloat16(kpv);
    if (c == 0) g_omega[m] = 0.05f * stm_h[s];
}

// ---- 4 (S1): bf16 HMMA screen, CTA 128m x 128j ------------------------------
__global__ void __launch_bounds__(256) k_simsT() {
    __shared__ __align__(16) unsigned sA32[128 * 40];
    __shared__ __align__(16) unsigned sB32[128 * 40];
    __shared__ unsigned s_max[128];
    const int tid = threadIdx.x, wid = tid >> 5, l = tid & 31;
    const int warp_m = wid >> 2, warp_n = wid & 3;
    const int m0 = blockIdx.x * 128;
    const int ns = g_scal[5];

    {   // A fill: 128 rows x 32 u32, permuted
        const unsigned* src = (const unsigned*)(g_kpB + (size_t)m0 * 64);
        #pragma unroll
        for (int i = 0; i < 16; ++i) {
            int idx = tid + i * 256;
            int row = idx >> 5, cu = idx & 31;
            sA32[row * 40 + kperm(cu)] = src[idx];
        }
    }

    float runmax = -3.0f;

    for (int t = blockIdx.y; t < ns; t += (int)gridDim.y) {
        __syncthreads();
        {
            const unsigned* src = (const unsigned*)(g_lknB + (size_t)t * 128 * 64);
            #pragma unroll
            for (int i = 0; i < 16; ++i) {
                int idx = tid + i * 256;
                int row = idx >> 5, cu = idx & 31;
                sB32[row * 40 + kperm(cu)] = __ldg(&src[idx]);
            }
        }
        if (tid < 128) s_max[tid] = 0u;
        __syncthreads();

        float acc[4][4][4];
        #pragma unroll
        for (int i = 0; i < 4; ++i)
            #pragma unroll
            for (int q = 0; q < 4; ++q)
                #pragma unroll
                for (int r = 0; r < 4; ++r) acc[i][q][r] = 0.0f;

        #pragma unroll
        for (int ch = 0; ch < 4; ++ch) {
            unsigned a[4][4], b[4][2];
            int cb = ch * 8 + (l & 3) * 2;
            #pragma unroll
            for (int i = 0; i < 4; ++i) {
                int r0 = warp_m * 64 + i * 16 + (l >> 2);
                unsigned long long v0 =
                    *reinterpret_cast<const unsigned long long*>(&sA32[r0 * 40 + cb]);
                unsigned long long v1 =
                    *reinterpret_cast<const unsigned long long*>(&sA32[(r0 + 8) * 40 + cb]);
                a[i][0] = (unsigned)v0; a[i][2] = (unsigned)(v0 >> 32);
                a[i][1] = (unsigned)v1; a[i][3] = (unsigned)(v1 >> 32);
            }
            #pragma unroll
            for (int q = 0; q < 4; ++q) {
                int rb = warp_n * 32 + q * 8 + (l >> 2);
                unsigned long long v =
                    *reinterpret_cast<const unsigned long long*>(&sB32[rb * 40 + cb]);
                b[q][0] = (unsigned)v; b[q][1] = (unsigned)(v >> 32);
            }
            #pragma unroll
            for (int i = 0; i < 4; ++i)
                #pragma unroll
                for (int q = 0; q < 4; ++q)
                    mma16816(acc[i][q], a[i], b[q]);
        }

        #pragma unroll
        for (int i = 0; i < 4; ++i) {
            float t0 = -3.0f, t1 = -3.0f;
            #pragma unroll
            for (int q = 0; q < 4; ++q) {
                t0 = fmaxf(t0, fmaxf(acc[i][q][0], acc[i][q][1]));
                t1 = fmaxf(t1, fmaxf(acc[i][q][2], acc[i][q][3]));
            }
            t0 = fmaxf(t0, __shfl_xor_sync(0xFFFFFFFFu, t0, 1));
            t0 = fmaxf(t0, __shfl_xor_sync(0xFFFFFFFFu, t0, 2));
            t1 = fmaxf(t1, __shfl_xor_sync(0xFFFFFFFFu, t1, 1));
            t1 = fmaxf(t1, __shfl_xor_sync(0xFFFFFFFFu, t1, 2));
            if ((l & 3) == 0) {
                int r0 = warp_m * 64 + i * 16 + (l >> 2);
                atomicMax(&s_max[r0], fmono(t0));
                atomicMax(&s_max[r0 + 8], fmono(t1));
            }
        }
        __syncthreads();
        if (tid < 128) {
            float v = funmono(s_max[tid]);
            g_smax[(size_t)(m0 + tid) * NSMAX + t] = v;
            runmax = fmaxf(runmax, v);
        }
    }
    if (tid < 128) atomicMax(&g_gmaxU[m0 + tid], fmono(runmax));
}

// ---- 5 (S2): exact fp32 recheck + fused matched scatter --------------------
__global__ void k_exmat(const float* __restrict__ stm_V, const float* __restrict__ stm_e,
                        const float* __restrict__ stm_h,
                        float* __restrict__ oK, float* __restrict__ oV,
                        float* __restrict__ oe, float* __restrict__ oh) {
    int wid = threadIdx.x >> 5, lane = threadIdx.x & 31;
    int m = blockIdx.x * 8 + wid;
    int ns = g_scal[5];
    float thr = funmono(g_gmaxU[m]) - 0.01f;
    float4 kp4[16];
    const float4* kpr = reinterpret_cast<const float4*>(g_kpN + m * 64);
    #pragma unroll
    for (int i = 0; i < 16; ++i) kp4[i] = kpr[i];
    unsigned long long best = 0ull;
    for (int t = 0; t < ns; ++t) {
        if (g_smax[(size_t)m * NSMAX + t] < thr) continue;
        #pragma unroll
        for (int q = 0; q < 4; ++q) {
            int j = t * 128 + lane + q * 32;
            const float4* br = reinterpret_cast<const float4*>(g_lknC + (size_t)j * 64);
            float dot = 0.f;
            #pragma unroll
            for (int i = 0; i < 16; ++i) {
                float4 b4 = br[i];
                dot = fmaf(kp4[i].x, b4.x, dot);
                dot = fmaf(kp4[i].y, b4.y, dot);
                dot = fmaf(kp4[i].z, b4.z, dot);
                dot = fmaf(kp4[i].w, b4.w, dot);
            }
            unsigned long long pk =
                ((unsigned long long)fmono(dot) << 32) | g_ajinv[j];
            if (pk > best) best = pk;
        }
    }
    #pragma unroll
    for (int off = 16; off; off >>= 1) {
        unsigned long long o = __shfl_xor_sync(0xFFFFFFFFu, best, off);
        if (o > best) best = o;
    }
    float sim = funmono((unsigned)(best >> 32));
    int j = (int)(0xFFFFFFFFu - (unsigned)(best & 0xFFFFFFFFull));
    bool matched = (sim >= 0.5f);
    int s = g_sel[m];
    float om = g_omega[m];
    if (lane == 0) {
        g_unm[m] = matched ? 0 : 1;
        g_key[m] = stm_key(s, stm_h[s]);
        g_gmaxU[m] = 0u;
        if (matched) atomicAdd(&oh[j], om);
    }
    if (matched) {
        #pragma unroll
        for (int q = 0; q < 2; ++q) {
            int c = lane + q * 32;
            atomicAdd(&oK[(size_t)j * 64 + c], om * g_Kproj[m * 64 + c]);
        }
        #pragma unroll
        for (int q = 0; q < 4; ++q) {
            int c = lane + q * 32;
            atomicAdd(&oV[(size_t)j * 128 + c], om * stm_V[(size_t)s * 128 + c]);
        }
        if (lane < 4) atomicAdd(&oe[(size_t)j * 4 + lane], om * stm_e[(size_t)s * 4 + lane]);
    }
}

// ---- 6: rank unmatched (h desc, idx asc) -------------------------------------
__global__ void k_rank() {
    __shared__ unsigned long long sk[TOP_M];
    __shared__ unsigned char su[TOP_M];
    int t = threadIdx.x;
    for (int i = t; i < TOP_M; i += 256) { sk[i] = g_key[i]; su[i] = (unsigned char)g_unm[i]; }
    __syncthreads();
    int m = blockIdx.x * 256 + t;
    if (g_unm[m]) {
        unsigned long long k = sk[m];
        int r = 0;
        for (int i = 0; i < TOP_M; ++i) r += (su[i] && sk[i] > k);
        g_rank[m] = r;
    }
}

// ---- 7: unmatched fresh-slot writes (2048-way parallel) ----------------------
__global__ void k_unmatch(const float* __restrict__ stm_V, const float* __restrict__ stm_e,
                          float* __restrict__ oK, float* __restrict__ oV,
                          float* __restrict__ oe, float* __restrict__ oh) {
    int m = blockIdx.x;
    if (!g_unm[m]) return;
    int slot = g_free[g_rank[m]], c = threadIdx.x, s = g_sel[m];
    oK[(size_t)slot * 64 + c] = g_Kproj[m * 64 + c];
    oV[(size_t)slot * 128 + c] = stm_V[(size_t)s * 128 + c];
    oV[(size_t)slot * 128 + 64 + c] = stm_V[(size_t)s * 128 + 64 + c];
    if (c < 4) oe[(size_t)slot * 4 + c] = stm_e[(size_t)s * 4 + c];
    if (c == 0) oh[slot] = g_omega[m];
}

// ---- fused 3D gaussian blur + merge (branchless, div-free) -------------------
#define BLUR_SMEM ((10368 + 10368) * 4)   // 82944 B
__global__ void __launch_bounds__(256) k_blurAll(const float* __restrict__ stm_t,
                                                 const float* __restrict__ ltm_t,
                                                 float* __restrict__ oT) {
    extern __shared__ float p[];
    float* p0 = p;
    float* p0c = p + 576;
    float* p1 = p + 10368;
    float w[7], inv; gw(w, inv);
    int tid = threadIdx.x;
    int plane = blockIdx.x;
    int c = plane / 96, d = plane % 96;
    size_t cbase = (size_t)c * 96 * 9216;

    for (int i = tid; i < 576; i += 256) { p0[i] = 0.0f; p0[9792 + i] = 0.0f; }
    for (int i = tid; i < 1152; i += 256) {
        int row = i / 12, cc = i - row * 12;
        p1[row * 108 + (cc < 6 ? cc : 96 + cc)] = 0.0f;
    }

    float4 acc[9];
    #pragma unroll
    for (int e = 0; e < 9; ++e) acc[e] = make_float4(0.f, 0.f, 0.f, 0.f);
    #pragma unroll
    for (int t = -6; t <= 6; ++t) {
        int dd = d + t;
        if (dd < 0 || dd >= 96) continue;
        float ww = w[t < 0 ? -t : t];
        const float4* src = reinterpret_cast<const float4*>(stm_t + cbase + (size_t)dd * 9216);
        #pragma unroll
        for (int e = 0; e < 9; ++e) {
            float4 v = src[tid + e * 256];
            acc[e].x = fmaf(v.x, ww, acc[e].x);
            acc[e].y = fmaf(v.y, ww, acc[e].y);
            acc[e].z = fmaf(v.z, ww, acc[e].z);
            acc[e].w = fmaf(v.w, ww, acc[e].w);
        }
    }
    float4* d0 = reinterpret_cast<float4*>(p0c);
    #pragma unroll
    for (int e = 0; e < 9; ++e) {
        float4 v = acc[e];
        d0[tid + e * 256] = make_float4(v.x * inv, v.y * inv, v.z * inv, v.w * inv);
    }
    __syncthreads();

    {
        int h = tid / 96;
        int x = tid - h * 96;
        for (int i = tid; i < 9216; i += 256) {
            float a2 = p0c[i] * w[0];
            #pragma unroll
            for (int t = 1; t < 7; ++t)
                a2 += (p0c[i - t * 96] + p0c[i + t * 96]) * w[t];
            p1[h * 108 + 6 + x] = a2 * inv;
            x += 64; h += 2;
            if (x >= 96) { x -= 96; h += 1; }
        }
    }
    __syncthreads();

    {
        float xi = (c == 0) ? 0.005f : 0.003f;
        size_t base = cbase + (size_t)d * 9216;
        int h = tid / 96;
        int x = tid - h * 96;
        for (int i = tid; i < 9216; i += 256) {
            const float* row = p1 + h * 108 + 6 + x;
            float a2 = row[0] * w[0];
            #pragma unroll
            for (int t = 1; t < 7; ++t)
                a2 += (row[-t] + row[t]) * w[t];
            oT[base + i] = ltm_t[base + i] + xi * (a2 * inv);
            x += 64; h += 2;
            if (x >= 96) { x -= 96; h += 1; }
        }
    }
}

extern "C" void kernel_launch(void* const* d_in, const int* in_sizes, int n_in,
                              void* d_out, int out_size) {
    (void)in_sizes; (void)n_in; (void)out_size;
    const float* stm_K   = (const float*)d_in[0];
    const float* stm_V   = (const float*)d_in[1];
    const float* stm_e   = (const float*)d_in[2];
    const float* stm_h   = (const float*)d_in[3];
    const float* ltm_K   = (const float*)d_in[4];
    const float* ltm_V   = (const float*)d_in[5];
    const float* ltm_e   = (const float*)d_in[6];
    const float* ltm_h   = (const float*)d_in[7];
    const float* W       = (const float*)d_in[8];
    const float* b       = (const float*)d_in[9];
    const float* stm_t   = (const float*)d_in[10];
    const float* ltm_t   = (const float*)d_in[11];
    const float* fatigue = (const float*)d_in[12];
    const int*   stm_act = (const int*)d_in[13];
    const int*   ltm_act = (const int*)d_in[14];

    float* out = (float*)d_out;
    float* oK  = out;                 // 65536*64
    float* oV  = out + 4194304;       // 65536*128
    float* oe  = out + 12582912;      // 65536*4
    float* oh  = out + 12845056;      // 65536
    float* oSV = out + 12910592;      // 65536*128
    float* oT  = out + 21299200;      // 5*96^3
    float* oF  = out + 25722880;      // 1

    static cudaStream_t sB = 0, sD = 0;
    static cudaEvent_t eR = 0, eB = 0, eD = 0;
    static bool init_done = false;
    if (!init_done) {
        cudaFuncSetAttribute(k_blurAll, cudaFuncAttributeMaxDynamicSharedMemorySize, BLUR_SMEM);
        cudaStreamCreateWithFlags(&sB, cudaStreamNonBlocking);
        cudaStreamCreateWithFlags(&sD, cudaStreamNonBlocking);
        cudaEventCreateWithFlags(&eR, cudaEventDisableTiming);
        cudaEventCreateWithFlags(&eB, cudaEventDisableTiming);
        cudaEventCreateWithFlags(&eD, cudaEventDisableTiming);
        init_done = true;
    }

    // fork
    cudaEventRecord(eR, 0);
    cudaStreamWaitEvent(sB, eR, 0);
    cudaStreamWaitEvent(sD, eR, 0);

    // side chains first so k_histlkn is the 4th enqueued kernel (ncu target)
    k_copy<<<12608, 256, 0, sB>>>((const float4*)ltm_K, (const float4*)ltm_V,
                                  (const float4*)ltm_e, (const float4*)ltm_h,
                                  (float4*)oK);
    cudaEventRecord(eB, sB);
    k_stmv<<<8192, 256, 0, sB>>>(stm_V, oSV);
    k_blurAll<<<480, 256, BLUR_SMEM, sD>>>(stm_t, ltm_t, oT);
    cudaEventRecord(eD, sD);

    // critical path
    k_histlkn<<<16384, 256>>>(ltm_K, ltm_act, stm_h, stm_act);   // launch #4
    k_prep<<<2, 1024>>>(fatigue, oF, ltm_act);
    k_compact<<<64, 1024>>>(stm_h, stm_act);
    k_proj<<<2048, 64>>>(stm_K, stm_h, W, b);
    k_simsT<<<dim3(16, 18), 256>>>();

    cudaStreamWaitEvent(0, eB, 0);
    k_exmat<<<256, 256>>>(stm_V, stm_e, stm_h, oK, oV, oe, oh);
    k_rank<<<8, 256>>>();
    k_unmatch<<<2048, 64>>>(stm_V, stm_e, oK, oV, oe, oh);

    // join remaining side chain (stmv completion implied by stream order? no —
    // eB was recorded before stmv; join sB tail explicitly)
    cudaEventRecord(eR, 0);  // reuse not allowed mid-graph; use dedicated join below
    cudaStreamWaitEvent(0, eD, 0);
    {
        static cudaEvent_t eB2 = 0;
        static bool e2init = false;
        if (!e2init) { cudaEventCreateWithFlags(&eB2, cudaEventDisableTiming); e2init = true; }
        cudaEventRecord(eB2, sB);
        cudaStreamWaitEvent(0, eB2, 0);
    }
}

// round 16
// speedup vs baseline: 1.8405x; 1.0461x over previous
#include <cuda_runtime.h>
#include <cuda_bf16.h>
#include <cstdint>
#include <math.h>

#define N_STM 65536
#define N_LTM 65536
#define TOP_M 2048
#define NBIN  4096
#define TVOL  (5*96*96*96)
#define NSMAX 516

// ---------------- scratch (static zero-init; replay-safe) -------------------
__device__ int                g_hist[NBIN];
__device__ int                g_scal[8];   // 0:T 1:cnt_above 2:sel_ctr 3:bnd_ctr 4:n_act 5:n_stages 6:done
__device__ int                g_sel[TOP_M];
__device__ int                g_boundary[N_STM];
__device__ float              g_Kproj[TOP_M*64];
__device__ float              g_kpN[TOP_M*64];
__device__ __align__(16) __nv_bfloat16 g_kpB[TOP_M*64];
__device__ float              g_omega[TOP_M];
__device__ __align__(16) float g_lknC[(size_t)(N_LTM+128)*64];
__device__ __align__(16) __nv_bfloat16 g_lknB[(size_t)(N_LTM+128)*64];
__device__ unsigned           g_ajinv[N_LTM+128];
__device__ float              g_smax[(size_t)TOP_M*NSMAX];
__device__ unsigned           g_gmaxU[TOP_M];
__device__ unsigned long long g_key[TOP_M];
__device__ int                g_unm[TOP_M];
__device__ int                g_rank[TOP_M];
__device__ int                g_free[TOP_M];

// ---------------- helpers ---------------------------------------------------
__device__ __forceinline__ unsigned fmono(float f) {
    unsigned u = __float_as_uint(f);
    return (u & 0x80000000u) ? ~u : (u | 0x80000000u);
}
__device__ __forceinline__ float funmono(unsigned m) {
    unsigned u = (m & 0x80000000u) ? (m ^ 0x80000000u) : ~m;
    return __uint_as_float(u);
}
__device__ __forceinline__ unsigned long long stm_key(int i, float h) {
    return ((unsigned long long)__float_as_uint(h) << 32) | (0xFFFFFFFFu - (unsigned)i);
}
__device__ __forceinline__ int hbin(float h) {
    return min(max((int)(h * (float)NBIN), 0), NBIN - 1);
}
__device__ __forceinline__ void gw(float* w, float& inv) {
    w[0] = 1.0f; float sum = 1.0f;
    #pragma unroll
    for (int i = 1; i < 7; ++i) {
        w[i] = expf(-0.5f * (float)(i * i) / 4.0f);
        sum += 2.0f * w[i];
    }
    inv = 1.0f / sum;
}
__device__ __forceinline__ void mma16816(float* c, const unsigned* a, const unsigned* b) {
    asm volatile("mma.sync.aligned.m16n8k16.row.col.f32.bf16.bf16.f32 "
                 "{%0,%1,%2,%3}, {%4,%5,%6,%7}, {%8,%9}, {%0,%1,%2,%3};"
                 : "+f"(c[0]), "+f"(c[1]), "+f"(c[2]), "+f"(c[3])
                 : "r"(a[0]), "r"(a[1]), "r"(a[2]), "r"(a[3]), "r"(b[0]), "r"(b[1]));
}
__device__ __forceinline__ int kperm(int cu) {
    return (cu & ~7) + ((cu & 3) * 2 + ((cu >> 2) & 1));
}
__device__ __forceinline__ unsigned packbf2(float a, float b) {
    __nv_bfloat16 b0 = __float2bfloat16(a), b1 = __float2bfloat16(b);
    unsigned short u0, u1;
    memcpy(&u0, &b0, 2); memcpy(&u1, &b1, 2);
    return (unsigned)u0 | ((unsigned)u1 << 16);
}

// ---- base-state copy: 4 float4 per thread (MLP=4) ---------------------------
#define COPY_STRIDE 806912   // 3227648/4
__global__ void k_copy(const float4* __restrict__ K, const float4* __restrict__ V,
                       const float4* __restrict__ e, const float4* __restrict__ h,
                       float4* __restrict__ out) {
    int base = blockIdx.x * 256 + threadIdx.x;
    #pragma unroll
    for (int it = 0; it < 4; ++it) {
        int i = base + it * COPY_STRIDE;
        float4 v;
        if (i < 1048576)       v = K[i];
        else if (i < 3145728)  v = V[i - 1048576];
        else if (i < 3211264)  v = e[i - 3145728];
        else                   v = h[i - 3211264];
        out[i] = v;
    }
}

// ---- stm_V norm clip: 8 threads/row, 4 float4 each (MLP=4) -----------------
__global__ void k_stmv(const float4* __restrict__ sv4, float4* __restrict__ o4) {
    int tid = threadIdx.x;
    int rl = tid >> 3, l8 = tid & 7;
    size_t row = (size_t)blockIdx.x * 32 + rl;
    const float4* src = sv4 + row * 32;
    float4 v[4];
    #pragma unroll
    for (int it = 0; it < 4; ++it) v[it] = src[l8 + it * 8];
    float sq = 0.f;
    #pragma unroll
    for (int it = 0; it < 4; ++it)
        sq += v[it].x*v[it].x + v[it].y*v[it].y + v[it].z*v[it].z + v[it].w*v[it].w;
    #pragma unroll
    for (int off = 4; off; off >>= 1) sq += __shfl_xor_sync(0xFFFFFFFFu, sq, off);
    float sc = fminf(1.0f, 2.0f / (sqrtf(sq) + 1e-8f));
    float4* dst = o4 + row * 32;
    #pragma unroll
    for (int it = 0; it < 4; ++it)
        dst[l8 + it * 8] = make_float4(v[it].x*sc, v[it].y*sc, v[it].z*sc, v[it].w*sc);
}

// ---- 1: ltm_K normalize + compaction (float4) | stm histogram ---------------
__global__ void k_histlkn(const float4* __restrict__ ltm_K4, const int* __restrict__ ltm_act,
                          const float* __restrict__ stm_h, const int* __restrict__ stm_act) {
    __shared__ int sact[16];
    __shared__ int sbase;
    int tid = threadIdx.x;
    int rl = tid >> 4, l16 = tid & 15;
    int j = blockIdx.x * 16 + rl;
    float4 v = ltm_K4[(size_t)j * 16 + l16];
    float sq = v.x*v.x + v.y*v.y + v.z*v.z + v.w*v.w;
    #pragma unroll
    for (int off = 8; off; off >>= 1) sq += __shfl_xor_sync(0xFFFFFFFFu, sq, off);
    int a = (ltm_act[j] > 0) ? 1 : 0;
    if (l16 == 0) sact[rl] = a;
    __syncthreads();
    int tot = 0, pre = 0;
    #pragma unroll
    for (int x = 0; x < 16; ++x) { int c = sact[x]; tot += c; if (x < rl) pre += c; }
    if (tid == 0) sbase = tot ? atomicAdd(&g_scal[4], tot) : 0;
    __syncthreads();
    if (a) {
        int pos = sbase + pre;
        float inv = 1.0f / (sqrtf(sq) + 1e-8f);
        float4 nv = make_float4(v.x*inv, v.y*inv, v.z*inv, v.w*inv);
        reinterpret_cast<float4*>(g_lknC)[(size_t)pos * 16 + l16] = nv;
        uint2 pb = make_uint2(packbf2(nv.x, nv.y), packbf2(nv.z, nv.w));
        reinterpret_cast<uint2*>(g_lknB)[(size_t)pos * 16 + l16] = pb;
        if (l16 == 0) g_ajinv[pos] = 0xFFFFFFFFu - (unsigned)j;
    }
    int i = blockIdx.x * 256 + tid;
    if (i < N_STM && stm_act[i] > 0) atomicAdd(&g_hist[hbin(stm_h[i])], 1);
}

// ---- 2: block 0 = threshold + pad; block 1 = freeslots ---------------------
__global__ void k_prep(const float* __restrict__ fat, float* __restrict__ oF,
                       const int* __restrict__ ltm_act) {
    int t = threadIdx.x;
    if (blockIdx.x == 1) {
        int w = t >> 5, lane = t & 31;
        __shared__ int wcnt[32];
        int running = 0;
        for (int tile = 0; tile < 64 && running < TOP_M; ++tile) {
            int i = tile * 1024 + t;
            int inact = (ltm_act[i] == 0);
            unsigned bal = __ballot_sync(0xFFFFFFFFu, inact);
            if (lane == 0) wcnt[w] = __popc(bal);
            __syncthreads();
            int pre = 0, total = 0;
            #pragma unroll
            for (int x = 0; x < 32; ++x) {
                int cx = wcnt[x];
                if (x < w) pre += cx;
                total += cx;
            }
            int pos = running + pre + __popc(bal & ((1u << lane) - 1));
            if (inact && pos < TOP_M) g_free[pos] = i;
            running += total;
            __syncthreads();
        }
        return;
    }
    __shared__ int s[1024];
    int base = NBIN - 1 - 4 * t;
    int h0 = g_hist[base], h1 = g_hist[base-1], h2 = g_hist[base-2], h3 = g_hist[base-3];
    g_hist[base] = 0; g_hist[base-1] = 0; g_hist[base-2] = 0; g_hist[base-3] = 0;
    int sum = h0 + h1 + h2 + h3;
    s[t] = sum;
    __syncthreads();
    for (int off = 1; off < 1024; off <<= 1) {
        int v = s[t], a2 = (t >= off) ? s[t - off] : 0;
        __syncthreads(); s[t] = v + a2; __syncthreads();
    }
    int c = s[t] - sum;
    int hh[4] = {h0, h1, h2, h3};
    #pragma unroll
    for (int q = 0; q < 4; ++q) {
        if (c < TOP_M && c + hh[q] >= TOP_M) { g_scal[0] = base - q; g_scal[1] = c; }
        c += hh[q];
    }
    int n_act = g_scal[4];
    for (int idx = t; idx < 128 * 64; idx += 1024) {
        g_lknC[(size_t)n_act * 64 + idx] = 0.0f;
        g_lknB[(size_t)n_act * 64 + idx] = __float2bfloat16(0.0f);
    }
    if (t < 128) g_ajinv[n_act + t] = 0u;
    if (t == 0) {
        g_scal[5] = (n_act + 127) >> 7;
        g_scal[4] = 0;   // restore for replay
        oF[0] = 0.2f * fat[0];
    }
}

// ---- 2b: grid-parallel top-M classification + last-block tie-break ---------
__global__ void k_compact(const float* __restrict__ h, const int* __restrict__ act) {
    __shared__ int sdone;
    int t = threadIdx.x;
    int i = blockIdx.x * 1024 + t;
    int T = g_scal[0];
    if (act[i] > 0) {
        int bn = hbin(h[i]);
        if (bn > T)       g_sel[atomicAdd(&g_scal[2], 1)] = i;
        else if (bn == T) g_boundary[atomicAdd(&g_scal[3], 1)] = i;
    }
    __threadfence();
    __syncthreads();
    if (t == 0) sdone = atomicAdd(&g_scal[6], 1);
    __syncthreads();
    if (sdone == 63) {
        int B = g_scal[3], need = TOP_M - g_scal[1];
        for (int cc = t; cc < B; cc += 1024) {
            int ii = g_boundary[cc];
            unsigned long long k = stm_key(ii, h[ii]);
            int r = 0;
            for (int q = 0; q < B; ++q) {
                int i2 = g_boundary[q];
                r += (stm_key(i2, h[i2]) > k);
            }
            if (r < need) g_sel[atomicAdd(&g_scal[2], 1)] = ii;
        }
        __syncthreads();
        if (t == 0) { g_scal[2] = 0; g_scal[3] = 0; g_scal[6] = 0; }
    }
}

// ---- 3: projection + kp normalize (fp32 + bf16) ----------------------------
__global__ void k_proj(const float* __restrict__ stm_K, const float* __restrict__ stm_h,
                       const float* __restrict__ W, const float* __restrict__ b) {
    int m = blockIdx.x, c = threadIdx.x;
    __shared__ float sK[16];
    __shared__ float ws[2];
    int s = g_sel[m];
    if (c < 16) sK[c] = stm_K[(size_t)s * 16 + c];
    __syncthreads();
    float acc = b[c];
    #pragma unroll
    for (int k = 0; k < 16; ++k) acc = fmaf(sK[k], W[k * 64 + c], acc);
    float sq = acc * acc;
    #pragma unroll
    for (int off = 16; off; off >>= 1) sq += __shfl_xor_sync(0xFFFFFFFFu, sq, off);
    if ((c & 31) == 0) ws[c >> 5] = sq;
    __syncthreads();
    float kpv = acc / (sqrtf(ws[0] + ws[1]) + 1e-8f);
    g_Kproj[m * 64 + c] = acc;
    g_kpN[m * 64 + c] = kpv;
    g_kpB[m * 64 + c] = __float2bfloat16(kpv);
    if (c == 0) g_omega[m] = 0.05f * stm_h[s];
}

// ---- 4 (S1): bf16 HMMA screen, CTA 128m x 128j ------------------------------
__global__ void __launch_bounds__(256) k_simsT() {
    __shared__ __align__(16) unsigned sA32[128 * 40];
    __shared__ __align__(16) unsigned sB32[128 * 40];
    __shared__ unsigned s_max[128];
    const int tid = threadIdx.x, wid = tid >> 5, l = tid & 31;
    const int warp_m = wid >> 2, warp_n = wid & 3;
    const int m0 = blockIdx.x * 128;
    const int ns = g_scal[5];

    {
        const unsigned* src = (const unsigned*)(g_kpB + (size_t)m0 * 64);
        #pragma unroll
        for (int i = 0; i < 16; ++i) {
            int idx = tid + i * 256;
            int row = idx >> 5, cu = idx & 31;
            sA32[row * 40 + kperm(cu)] = src[idx];
        }
    }

    float runmax = -3.0f;

    for (int t = blockIdx.y; t < ns; t += (int)gridDim.y) {
        __syncthreads();
        {
            const unsigned* src = (const unsigned*)(g_lknB + (size_t)t * 128 * 64);
            #pragma unroll
            for (int i = 0; i < 16; ++i) {
                int idx = tid + i * 256;
                int row = idx >> 5, cu = idx & 31;
                sB32[row * 40 + kperm(cu)] = __ldg(&src[idx]);
            }
        }
        if (tid < 128) s_max[tid] = 0u;
        __syncthreads();

        float acc[4][4][4];
        #pragma unroll
        for (int i = 0; i < 4; ++i)
            #pragma unroll
            for (int q = 0; q < 4; ++q)
                #pragma unroll
                for (int r = 0; r < 4; ++r) acc[i][q][r] = 0.0f;

        #pragma unroll
        for (int ch = 0; ch < 4; ++ch) {
            unsigned a[4][4], b[4][2];
            int cb = ch * 8 + (l & 3) * 2;
            #pragma unroll
            for (int i = 0; i < 4; ++i) {
                int r0 = warp_m * 64 + i * 16 + (l >> 2);
                unsigned long long v0 =
                    *reinterpret_cast<const unsigned long long*>(&sA32[r0 * 40 + cb]);
                unsigned long long v1 =
                    *reinterpret_cast<const unsigned long long*>(&sA32[(r0 + 8) * 40 + cb]);
                a[i][0] = (unsigned)v0; a[i][2] = (unsigned)(v0 >> 32);
                a[i][1] = (unsigned)v1; a[i][3] = (unsigned)(v1 >> 32);
            }
            #pragma unroll
            for (int q = 0; q < 4; ++q) {
                int rb = warp_n * 32 + q * 8 + (l >> 2);
                unsigned long long v =
                    *reinterpret_cast<const unsigned long long*>(&sB32[rb * 40 + cb]);
                b[q][0] = (unsigned)v; b[q][1] = (unsigned)(v >> 32);
            }
            #pragma unroll
            for (int i = 0; i < 4; ++i)
                #pragma unroll
                for (int q = 0; q < 4; ++q)
                    mma16816(acc[i][q], a[i], b[q]);
        }

        #pragma unroll
        for (int i = 0; i < 4; ++i) {
            float t0 = -3.0f, t1 = -3.0f;
            #pragma unroll
            for (int q = 0; q < 4; ++q) {
                t0 = fmaxf(t0, fmaxf(acc[i][q][0], acc[i][q][1]));
                t1 = fmaxf(t1, fmaxf(acc[i][q][2], acc[i][q][3]));
            }
            t0 = fmaxf(t0, __shfl_xor_sync(0xFFFFFFFFu, t0, 1));
            t0 = fmaxf(t0, __shfl_xor_sync(0xFFFFFFFFu, t0, 2));
            t1 = fmaxf(t1, __shfl_xor_sync(0xFFFFFFFFu, t1, 1));
            t1 = fmaxf(t1, __shfl_xor_sync(0xFFFFFFFFu, t1, 2));
            if ((l & 3) == 0) {
                int r0 = warp_m * 64 + i * 16 + (l >> 2);
                atomicMax(&s_max[r0], fmono(t0));
                atomicMax(&s_max[r0 + 8], fmono(t1));
            }
        }
        __syncthreads();
        if (tid < 128) {
            float v = funmono(s_max[tid]);
            g_smax[(size_t)(m0 + tid) * NSMAX + t] = v;
            runmax = fmaxf(runmax, v);
        }
    }
    if (tid < 128) atomicMax(&g_gmaxU[m0 + tid], fmono(runmax));
}

// ---- 5 (S2): exact fp32 recheck + fused matched scatter --------------------
__global__ void k_exmat(const float* __restrict__ stm_V, const float* __restrict__ stm_e,
                        const float* __restrict__ stm_h,
                        float* __restrict__ oK, float* __restrict__ oV,
                        float* __restrict__ oe, float* __restrict__ oh) {
    int wid = threadIdx.x >> 5, lane = threadIdx.x & 31;
    int m = blockIdx.x * 8 + wid;
    int ns = g_scal[5];
    float thr = funmono(g_gmaxU[m]) - 0.01f;
    float4 kp4[16];
    const float4* kpr = reinterpret_cast<const float4*>(g_kpN + m * 64);
    #pragma unroll
    for (int i = 0; i < 16; ++i) kp4[i] = kpr[i];
    unsigned long long best = 0ull;
    for (int t = 0; t < ns; ++t) {
        if (g_smax[(size_t)m * NSMAX + t] < thr) continue;
        #pragma unroll
        for (int q = 0; q < 4; ++q) {
            int j = t * 128 + lane + q * 32;
            const float4* br = reinterpret_cast<const float4*>(g_lknC + (size_t)j * 64);
            float dot = 0.f;
            #pragma unroll
            for (int i = 0; i < 16; ++i) {
                float4 b4 = br[i];
                dot = fmaf(kp4[i].x, b4.x, dot);
                dot = fmaf(kp4[i].y, b4.y, dot);
                dot = fmaf(kp4[i].z, b4.z, dot);
                dot = fmaf(kp4[i].w, b4.w, dot);
            }
            unsigned long long pk =
                ((unsigned long long)fmono(dot) << 32) | g_ajinv[j];
            if (pk > best) best = pk;
        }
    }
    #pragma unroll
    for (int off = 16; off; off >>= 1) {
        unsigned long long o = __shfl_xor_sync(0xFFFFFFFFu, best, off);
        if (o > best) best = o;
    }
    float sim = funmono((unsigned)(best >> 32));
    int j = (int)(0xFFFFFFFFu - (unsigned)(best & 0xFFFFFFFFull));
    bool matched = (sim >= 0.5f);
    int s = g_sel[m];
    float om = g_omega[m];
    if (lane == 0) {
        g_unm[m] = matched ? 0 : 1;
        g_key[m] = stm_key(s, stm_h[s]);
        g_gmaxU[m] = 0u;
        if (matched) atomicAdd(&oh[j], om);
    }
    if (matched) {
        #pragma unroll
        for (int q = 0; q < 2; ++q) {
            int c = lane + q * 32;
            atomicAdd(&oK[(size_t)j * 64 + c], om * g_Kproj[m * 64 + c]);
        }
        #pragma unroll
        for (int q = 0; q < 4; ++q) {
            int c = lane + q * 32;
            atomicAdd(&oV[(size_t)j * 128 + c], om * stm_V[(size_t)s * 128 + c]);
        }
        if (lane < 4) atomicAdd(&oe[(size_t)j * 4 + lane], om * stm_e[(size_t)s * 4 + lane]);
    }
}

// ---- 6: rank unmatched (h desc, idx asc) -------------------------------------
__global__ void k_rank() {
    __shared__ unsigned long long sk[TOP_M];
    __shared__ unsigned char su[TOP_M];
    int t = threadIdx.x;
    for (int i = t; i < TOP_M; i += 256) { sk[i] = g_key[i]; su[i] = (unsigned char)g_unm[i]; }
    __syncthreads();
    int m = blockIdx.x * 256 + t;
    if (g_unm[m]) {
        unsigned long long k = sk[m];
        int r = 0;
        for (int i = 0; i < TOP_M; ++i) r += (su[i] && sk[i] > k);
        g_rank[m] = r;
    }
}

// ---- 7: unmatched fresh-slot writes (2048-way parallel) ----------------------
__global__ void k_unmatch(const float* __restrict__ stm_V, const float* __restrict__ stm_e,
                          float* __restrict__ oK, float* __restrict__ oV,
                          float* __restrict__ oe, float* __restrict__ oh) {
    int m = blockIdx.x;
    if (!g_unm[m]) return;
    int slot = g_free[g_rank[m]], c = threadIdx.x, s = g_sel[m];
    oK[(size_t)slot * 64 + c] = g_Kproj[m * 64 + c];
    oV[(size_t)slot * 128 + c] = stm_V[(size_t)s * 128 + c];
    oV[(size_t)slot * 128 + 64 + c] = stm_V[(size_t)s * 128 + 64 + c];
    if (c < 4) oe[(size_t)slot * 4 + c] = stm_e[(size_t)s * 4 + c];
    if (c == 0) oh[slot] = g_omega[m];
}

// ---- fused 3D gaussian blur + merge (branchless, div-free) -------------------
#define BLUR_SMEM ((10368 + 10368) * 4)   // 82944 B
__global__ void __launch_bounds__(256) k_blurAll(const float* __restrict__ stm_t,
                                                 const float* __restrict__ ltm_t,
                                                 float* __restrict__ oT) {
    extern __shared__ float p[];
    float* p0 = p;
    float* p0c = p + 576;
    float* p1 = p + 10368;
    float w[7], inv; gw(w, inv);
    int tid = threadIdx.x;
    int plane = blockIdx.x;
    int c = plane / 96, d = plane % 96;
    size_t cbase = (size_t)c * 96 * 9216;

    for (int i = tid; i < 576; i += 256) { p0[i] = 0.0f; p0[9792 + i] = 0.0f; }
    for (int i = tid; i < 1152; i += 256) {
        int row = i / 12, cc = i - row * 12;
        p1[row * 108 + (cc < 6 ? cc : 96 + cc)] = 0.0f;
    }

    float4 acc[9];
    #pragma unroll
    for (int e = 0; e < 9; ++e) acc[e] = make_float4(0.f, 0.f, 0.f, 0.f);
    #pragma unroll
    for (int t = -6; t <= 6; ++t) {
        int dd = d + t;
        if (dd < 0 || dd >= 96) continue;
        float ww = w[t < 0 ? -t : t];
        const float4* src = reinterpret_cast<const float4*>(stm_t + cbase + (size_t)dd * 9216);
        #pragma unroll
        for (int e = 0; e < 9; ++e) {
            float4 v = src[tid + e * 256];
            acc[e].x = fmaf(v.x, ww, acc[e].x);
            acc[e].y = fmaf(v.y, ww, acc[e].y);
            acc[e].z = fmaf(v.z, ww, acc[e].z);
            acc[e].w = fmaf(v.w, ww, acc[e].w);
        }
    }
    float4* d0 = reinterpret_cast<float4*>(p0c);
    #pragma unroll
    for (int e = 0; e < 9; ++e) {
        float4 v = acc[e];
        d0[tid + e * 256] = make_float4(v.x * inv, v.y * inv, v.z * inv, v.w * inv);
    }
    __syncthreads();

    {
        int h = tid / 96;
        int x = tid - h * 96;
        for (int i = tid; i < 9216; i += 256) {
            float a2 = p0c[i] * w[0];
            #pragma unroll
            for (int t = 1; t < 7; ++t)
                a2 += (p0c[i - t * 96] + p0c[i + t * 96]) * w[t];
            p1[h * 108 + 6 + x] = a2 * inv;
            x += 64; h += 2;
            if (x >= 96) { x -= 96; h += 1; }
        }
    }
    __syncthreads();

    {
        float xi = (c == 0) ? 0.005f : 0.003f;
        size_t base = cbase + (size_t)d * 9216;
        int h = tid / 96;
        int x = tid - h * 96;
        for (int i = tid; i < 9216; i += 256) {
            const float* row = p1 + h * 108 + 6 + x;
            float a2 = row[0] * w[0];
            #pragma unroll
            for (int t = 1; t < 7; ++t)
                a2 += (row[-t] + row[t]) * w[t];
            oT[base + i] = ltm_t[base + i] + xi * (a2 * inv);
            x += 64; h += 2;
            if (x >= 96) { x -= 96; h += 1; }
        }
    }
}

extern "C" void kernel_launch(void* const* d_in, const int* in_sizes, int n_in,
                              void* d_out, int out_size) {
    (void)in_sizes; (void)n_in; (void)out_size;
    const float* stm_K   = (const float*)d_in[0];
    const float* stm_V   = (const float*)d_in[1];
    const float* stm_e   = (const float*)d_in[2];
    const float* stm_h   = (const float*)d_in[3];
    const float* ltm_K   = (const float*)d_in[4];
    const float* ltm_V   = (const float*)d_in[5];
    const float* ltm_e   = (const float*)d_in[6];
    const float* ltm_h   = (const float*)d_in[7];
    const float* W       = (const float*)d_in[8];
    const float* b       = (const float*)d_in[9];
    const float* stm_t   = (const float*)d_in[10];
    const float* ltm_t   = (const float*)d_in[11];
    const float* fatigue = (const float*)d_in[12];
    const int*   stm_act = (const int*)d_in[13];
    const int*   ltm_act = (const int*)d_in[14];

    float* out = (float*)d_out;
    float* oK  = out;                 // 65536*64
    float* oV  = out + 4194304;       // 65536*128
    float* oe  = out + 12582912;      // 65536*4
    float* oh  = out + 12845056;      // 65536
    float* oSV = out + 12910592;      // 65536*128
    float* oT  = out + 21299200;      // 5*96^3
    float* oF  = out + 25722880;      // 1

    static cudaStream_t sB = 0, sD = 0;
    static cudaEvent_t eR = 0, eB = 0, eB2 = 0, eD = 0;
    static bool init_done = false;
    if (!init_done) {
        cudaFuncSetAttribute(k_blurAll, cudaFuncAttributeMaxDynamicSharedMemorySize, BLUR_SMEM);
        cudaStreamCreateWithFlags(&sB, cudaStreamNonBlocking);
        cudaStreamCreateWithFlags(&sD, cudaStreamNonBlocking);
        cudaEventCreateWithFlags(&eR, cudaEventDisableTiming);
        cudaEventCreateWithFlags(&eB, cudaEventDisableTiming);
        cudaEventCreateWithFlags(&eB2, cudaEventDisableTiming);
        cudaEventCreateWithFlags(&eD, cudaEventDisableTiming);
        init_done = true;
    }

    // fork
    cudaEventRecord(eR, 0);
    cudaStreamWaitEvent(sB, eR, 0);
    cudaStreamWaitEvent(sD, eR, 0);

    // side chains first (k_histlkn = 4th enqueued kernel -> ncu target)
    k_copy<<<3152, 256, 0, sB>>>((const float4*)ltm_K, (const float4*)ltm_V,
                                 (const float4*)ltm_e, (const float4*)ltm_h,
                                 (float4*)oK);
    cudaEventRecord(eB, sB);             // exmat depends on base copy only
    k_stmv<<<2048, 256, 0, sB>>>((const float4*)stm_V, (float4*)oSV);
    cudaEventRecord(eB2, sB);
    k_blurAll<<<480, 256, BLUR_SMEM, sD>>>(stm_t, ltm_t, oT);
    cudaEventRecord(eD, sD);

    // critical path
    k_histlkn<<<4096, 256>>>((const float4*)ltm_K, ltm_act, stm_h, stm_act);  // #4
    k_prep<<<2, 1024>>>(fatigue, oF, ltm_act);
    k_compact<<<64, 1024>>>(stm_h, stm_act);
    k_proj<<<2048, 64>>>(stm_K, stm_h, W, b);
    k_simsT<<<dim3(16, 18), 256>>>();

    cudaStreamWaitEvent(0, eB, 0);
    k_exmat<<<256, 256>>>(stm_V, stm_e, stm_h, oK, oV, oe, oh);
    k_rank<<<8, 256>>>();
    k_unmatch<<<2048, 64>>>(stm_V, stm_e, oK, oV, oe, oh);

    // join side chains
    cudaStreamWaitEvent(0, eB2, 0);
    cudaStreamWaitEvent(0, eD, 0);
}

// round 17
// speedup vs baseline: 1.8551x; 1.0079x over previous
#include <cuda_runtime.h>
#include <cuda_bf16.h>
#include <cstdint>
#include <math.h>

#define N_STM 65536
#define N_LTM 65536
#define TOP_M 2048
#define NBIN  4096
#define TVOL  (5*96*96*96)
#define NSMAX 516

// ---------------- scratch (static zero-init; replay-safe) -------------------
__device__ int                g_hist[NBIN];
__device__ int                g_scal[8];   // 0:T 1:cnt_above 2:sel_ctr 3:bnd_ctr 4:n_act 5:n_stages 6:done
__device__ int                g_sel[TOP_M];
__device__ int                g_boundary[N_STM];
__device__ float              g_Kproj[TOP_M*64];
__device__ float              g_kpN[TOP_M*64];
__device__ __align__(16) __nv_bfloat16 g_kpB[TOP_M*64];
__device__ float              g_omega[TOP_M];
__device__ __align__(16) float g_lknC[(size_t)(N_LTM+128)*64];
__device__ __align__(16) __nv_bfloat16 g_lknB[(size_t)(N_LTM+128)*64];
__device__ unsigned           g_ajinv[N_LTM+128];
__device__ float              g_smax[(size_t)TOP_M*NSMAX];
__device__ unsigned           g_gmaxU[TOP_M];
__device__ unsigned long long g_key[TOP_M];
__device__ int                g_unm[TOP_M];
__device__ int                g_rank[TOP_M];
__device__ int                g_free[TOP_M];

// ---------------- helpers ---------------------------------------------------
__device__ __forceinline__ unsigned fmono(float f) {
    unsigned u = __float_as_uint(f);
    return (u & 0x80000000u) ? ~u : (u | 0x80000000u);
}
__device__ __forceinline__ float funmono(unsigned m) {
    unsigned u = (m & 0x80000000u) ? (m ^ 0x80000000u) : ~m;
    return __uint_as_float(u);
}
__device__ __forceinline__ unsigned long long stm_key(int i, float h) {
    return ((unsigned long long)__float_as_uint(h) << 32) | (0xFFFFFFFFu - (unsigned)i);
}
__device__ __forceinline__ int hbin(float h) {
    return min(max((int)(h * (float)NBIN), 0), NBIN - 1);
}
__device__ __forceinline__ void gw(float* w, float& inv) {
    w[0] = 1.0f; float sum = 1.0f;
    #pragma unroll
    for (int i = 1; i < 7; ++i) {
        w[i] = expf(-0.5f * (float)(i * i) / 4.0f);
        sum += 2.0f * w[i];
    }
    inv = 1.0f / sum;
}
__device__ __forceinline__ void mma16816(float* c, const unsigned* a, const unsigned* b) {
    asm volatile("mma.sync.aligned.m16n8k16.row.col.f32.bf16.bf16.f32 "
                 "{%0,%1,%2,%3}, {%4,%5,%6,%7}, {%8,%9}, {%0,%1,%2,%3};"
                 : "+f"(c[0]), "+f"(c[1]), "+f"(c[2]), "+f"(c[3])
                 : "r"(a[0]), "r"(a[1]), "r"(a[2]), "r"(a[3]), "r"(b[0]), "r"(b[1]));
}
__device__ __forceinline__ unsigned packbf2(float a, float b) {
    __nv_bfloat16 b0 = __float2bfloat16(a), b1 = __float2bfloat16(b);
    unsigned short u0, u1;
    memcpy(&u0, &b0, 2); memcpy(&u1, &b1, 2);
    return (unsigned)u0 | ((unsigned)u1 << 16);
}
// store uint4 (u32 cols 4*c4..4*c4+3) into kperm-permuted smem row
__device__ __forceinline__ void st_perm(unsigned* rowp, int c4, uint4 v) {
    int base8 = (c4 >> 1) * 8, odd = c4 & 1;
    rowp[base8 + odd + 0] = v.x;
    rowp[base8 + odd + 2] = v.y;
    rowp[base8 + odd + 4] = v.z;
    rowp[base8 + odd + 6] = v.w;
}

// ---- base-state copy: 4 float4 per thread (MLP=4) ---------------------------
#define COPY_STRIDE 806912   // 3227648/4
__global__ void k_copy(const float4* __restrict__ K, const float4* __restrict__ V,
                       const float4* __restrict__ e, const float4* __restrict__ h,
                       float4* __restrict__ out) {
    int base = blockIdx.x * 256 + threadIdx.x;
    #pragma unroll
    for (int it = 0; it < 4; ++it) {
        int i = base + it * COPY_STRIDE;
        float4 v;
        if (i < 1048576)       v = K[i];
        else if (i < 3145728)  v = V[i - 1048576];
        else if (i < 3211264)  v = e[i - 3145728];
        else                   v = h[i - 3211264];
        out[i] = v;
    }
}

// ---- stm_V norm clip: 8 threads/row, 4 float4 each (MLP=4) -----------------
__global__ void k_stmv(const float4* __restrict__ sv4, float4* __restrict__ o4) {
    int tid = threadIdx.x;
    int rl = tid >> 3, l8 = tid & 7;
    size_t row = (size_t)blockIdx.x * 32 + rl;
    const float4* src = sv4 + row * 32;
    float4 v[4];
    #pragma unroll
    for (int it = 0; it < 4; ++it) v[it] = src[l8 + it * 8];
    float sq = 0.f;
    #pragma unroll
    for (int it = 0; it < 4; ++it)
        sq += v[it].x*v[it].x + v[it].y*v[it].y + v[it].z*v[it].z + v[it].w*v[it].w;
    #pragma unroll
    for (int off = 4; off; off >>= 1) sq += __shfl_xor_sync(0xFFFFFFFFu, sq, off);
    float sc = fminf(1.0f, 2.0f / (sqrtf(sq) + 1e-8f));
    float4* dst = o4 + row * 32;
    #pragma unroll
    for (int it = 0; it < 4; ++it)
        dst[l8 + it * 8] = make_float4(v[it].x*sc, v[it].y*sc, v[it].z*sc, v[it].w*sc);
}

// ---- 1: ltm_K normalize + compaction (float4) | stm histogram ---------------
__global__ void k_histlkn(const float4* __restrict__ ltm_K4, const int* __restrict__ ltm_act,
                          const float* __restrict__ stm_h, const int* __restrict__ stm_act) {
    __shared__ int sact[16];
    __shared__ int sbase;
    int tid = threadIdx.x;
    int rl = tid >> 4, l16 = tid & 15;
    int j = blockIdx.x * 16 + rl;
    float4 v = ltm_K4[(size_t)j * 16 + l16];
    float sq = v.x*v.x + v.y*v.y + v.z*v.z + v.w*v.w;
    #pragma unroll
    for (int off = 8; off; off >>= 1) sq += __shfl_xor_sync(0xFFFFFFFFu, sq, off);
    int a = (ltm_act[j] > 0) ? 1 : 0;
    if (l16 == 0) sact[rl] = a;
    __syncthreads();
    int tot = 0, pre = 0;
    #pragma unroll
    for (int x = 0; x < 16; ++x) { int c = sact[x]; tot += c; if (x < rl) pre += c; }
    if (tid == 0) sbase = tot ? atomicAdd(&g_scal[4], tot) : 0;
    __syncthreads();
    if (a) {
        int pos = sbase + pre;
        float inv = 1.0f / (sqrtf(sq) + 1e-8f);
        float4 nv = make_float4(v.x*inv, v.y*inv, v.z*inv, v.w*inv);
        reinterpret_cast<float4*>(g_lknC)[(size_t)pos * 16 + l16] = nv;
        uint2 pb = make_uint2(packbf2(nv.x, nv.y), packbf2(nv.z, nv.w));
        reinterpret_cast<uint2*>(g_lknB)[(size_t)pos * 16 + l16] = pb;
        if (l16 == 0) g_ajinv[pos] = 0xFFFFFFFFu - (unsigned)j;
    }
    int i = blockIdx.x * 256 + tid;
    if (i < N_STM && stm_act[i] > 0) atomicAdd(&g_hist[hbin(stm_h[i])], 1);
}

// ---- 2: block 0 = threshold + pad; block 1 = freeslots ---------------------
__global__ void k_prep(const float* __restrict__ fat, float* __restrict__ oF,
                       const int* __restrict__ ltm_act) {
    int t = threadIdx.x;
    if (blockIdx.x == 1) {
        int w = t >> 5, lane = t & 31;
        __shared__ int wcnt[32];
        int running = 0;
        for (int tile = 0; tile < 64 && running < TOP_M; ++tile) {
            int i = tile * 1024 + t;
            int inact = (ltm_act[i] == 0);
            unsigned bal = __ballot_sync(0xFFFFFFFFu, inact);
            if (lane == 0) wcnt[w] = __popc(bal);
            __syncthreads();
            int pre = 0, total = 0;
            #pragma unroll
            for (int x = 0; x < 32; ++x) {
                int cx = wcnt[x];
                if (x < w) pre += cx;
                total += cx;
            }
            int pos = running + pre + __popc(bal & ((1u << lane) - 1));
            if (inact && pos < TOP_M) g_free[pos] = i;
            running += total;
            __syncthreads();
        }
        return;
    }
    __shared__ int s[1024];
    int base = NBIN - 1 - 4 * t;
    int h0 = g_hist[base], h1 = g_hist[base-1], h2 = g_hist[base-2], h3 = g_hist[base-3];
    g_hist[base] = 0; g_hist[base-1] = 0; g_hist[base-2] = 0; g_hist[base-3] = 0;
    int sum = h0 + h1 + h2 + h3;
    s[t] = sum;
    __syncthreads();
    for (int off = 1; off < 1024; off <<= 1) {
        int v = s[t], a2 = (t >= off) ? s[t - off] : 0;
        __syncthreads(); s[t] = v + a2; __syncthreads();
    }
    int c = s[t] - sum;
    int hh[4] = {h0, h1, h2, h3};
    #pragma unroll
    for (int q = 0; q < 4; ++q) {
        if (c < TOP_M && c + hh[q] >= TOP_M) { g_scal[0] = base - q; g_scal[1] = c; }
        c += hh[q];
    }
    int n_act = g_scal[4];
    for (int idx = t; idx < 128 * 64; idx += 1024) {
        g_lknC[(size_t)n_act * 64 + idx] = 0.0f;
        g_lknB[(size_t)n_act * 64 + idx] = __float2bfloat16(0.0f);
    }
    if (t < 128) g_ajinv[n_act + t] = 0u;
    if (t == 0) {
        g_scal[5] = (n_act + 127) >> 7;
        g_scal[4] = 0;   // restore for replay
        oF[0] = 0.2f * fat[0];
    }
}

// ---- 2b: grid-parallel top-M classification + last-block tie-break ---------
__global__ void k_compact(const float* __restrict__ h, const int* __restrict__ act) {
    __shared__ int sdone;
    int t = threadIdx.x;
    int i = blockIdx.x * 1024 + t;
    int T = g_scal[0];
    if (act[i] > 0) {
        int bn = hbin(h[i]);
        if (bn > T)       g_sel[atomicAdd(&g_scal[2], 1)] = i;
        else if (bn == T) g_boundary[atomicAdd(&g_scal[3], 1)] = i;
    }
    __threadfence();
    __syncthreads();
    if (t == 0) sdone = atomicAdd(&g_scal[6], 1);
    __syncthreads();
    if (sdone == 63) {
        int B = g_scal[3], need = TOP_M - g_scal[1];
        for (int cc = t; cc < B; cc += 1024) {
            int ii = g_boundary[cc];
            unsigned long long k = stm_key(ii, h[ii]);
            int r = 0;
            for (int q = 0; q < B; ++q) {
                int i2 = g_boundary[q];
                r += (stm_key(i2, h[i2]) > k);
            }
            if (r < need) g_sel[atomicAdd(&g_scal[2], 1)] = ii;
        }
        __syncthreads();
        if (t == 0) { g_scal[2] = 0; g_scal[3] = 0; g_scal[6] = 0; }
    }
}

// ---- 3: projection + kp normalize (fp32 + bf16) ----------------------------
__global__ void k_proj(const float* __restrict__ stm_K, const float* __restrict__ stm_h,
                       const float* __restrict__ W, const float* __restrict__ b) {
    int m = blockIdx.x, c = threadIdx.x;
    __shared__ float sK[16];
    __shared__ float ws[2];
    int s = g_sel[m];
    if (c < 16) sK[c] = stm_K[(size_t)s * 16 + c];
    __syncthreads();
    float acc = b[c];
    #pragma unroll
    for (int k = 0; k < 16; ++k) acc = fmaf(sK[k], W[k * 64 + c], acc);
    float sq = acc * acc;
    #pragma unroll
    for (int off = 16; off; off >>= 1) sq += __shfl_xor_sync(0xFFFFFFFFu, sq, off);
    if ((c & 31) == 0) ws[c >> 5] = sq;
    __syncthreads();
    float kpv = acc / (sqrtf(ws[0] + ws[1]) + 1e-8f);
    g_Kproj[m * 64 + c] = acc;
    g_kpN[m * 64 + c] = kpv;
    g_kpB[m * 64 + c] = __float2bfloat16(kpv);
    if (c == 0) g_omega[m] = 0.05f * stm_h[s];
}

// ---- 4 (S1): bf16 HMMA screen, CTA 128m x 128j, B double-buffered ----------
__global__ void __launch_bounds__(256) k_simsT() {
    __shared__ __align__(16) unsigned sA32[128 * 40];
    __shared__ __align__(16) unsigned sB32[128 * 40];
    __shared__ unsigned s_max[128];
    const int tid = threadIdx.x, wid = tid >> 5, l = tid & 31;
    const int warp_m = wid >> 2, warp_n = wid & 3;
    const int m0 = blockIdx.x * 128;
    const int ns = g_scal[5];

    {   // A fill: 1024 uint4, wide loads + permuted stores
        const uint4* src = (const uint4*)(g_kpB + (size_t)m0 * 64);
        #pragma unroll
        for (int it = 0; it < 4; ++it) {
            int idx4 = tid + it * 256;
            int row = idx4 >> 3, c4 = idx4 & 7;
            st_perm(&sA32[row * 40], c4, src[idx4]);
        }
    }

    float runmax = -3.0f;
    int t = blockIdx.y;
    uint4 pre[4];
    if (t < ns) {
        const uint4* src = (const uint4*)(g_lknB + (size_t)t * 128 * 64);
        #pragma unroll
        for (int it = 0; it < 4; ++it) pre[it] = __ldg(&src[tid + it * 256]);
    }

    for (; t < ns; ) {
        __syncthreads();   // previous compute done
        #pragma unroll
        for (int it = 0; it < 4; ++it) {
            int idx4 = tid + it * 256;
            int row = idx4 >> 3, c4 = idx4 & 7;
            st_perm(&sB32[row * 40], c4, pre[it]);
        }
        if (tid < 128) s_max[tid] = 0u;
        __syncthreads();

        int tn = t + (int)gridDim.y;
        if (tn < ns) {   // prefetch next stage during compute
            const uint4* src = (const uint4*)(g_lknB + (size_t)tn * 128 * 64);
            #pragma unroll
            for (int it = 0; it < 4; ++it) pre[it] = __ldg(&src[tid + it * 256]);
        }

        float acc[4][4][4];
        #pragma unroll
        for (int i = 0; i < 4; ++i)
            #pragma unroll
            for (int q = 0; q < 4; ++q)
                #pragma unroll
                for (int r = 0; r < 4; ++r) acc[i][q][r] = 0.0f;

        #pragma unroll
        for (int ch = 0; ch < 4; ++ch) {
            unsigned a[4][4], b[4][2];
            int cb = ch * 8 + (l & 3) * 2;
            #pragma unroll
            for (int i = 0; i < 4; ++i) {
                int r0 = warp_m * 64 + i * 16 + (l >> 2);
                unsigned long long v0 =
                    *reinterpret_cast<const unsigned long long*>(&sA32[r0 * 40 + cb]);
                unsigned long long v1 =
                    *reinterpret_cast<const unsigned long long*>(&sA32[(r0 + 8) * 40 + cb]);
                a[i][0] = (unsigned)v0; a[i][2] = (unsigned)(v0 >> 32);
                a[i][1] = (unsigned)v1; a[i][3] = (unsigned)(v1 >> 32);
            }
            #pragma unroll
            for (int q = 0; q < 4; ++q) {
                int rb = warp_n * 32 + q * 8 + (l >> 2);
                unsigned long long v =
                    *reinterpret_cast<const unsigned long long*>(&sB32[rb * 40 + cb]);
                b[q][0] = (unsigned)v; b[q][1] = (unsigned)(v >> 32);
            }
            #pragma unroll
            for (int i = 0; i < 4; ++i)
                #pragma unroll
                for (int q = 0; q < 4; ++q)
                    mma16816(acc[i][q], a[i], b[q]);
        }

        #pragma unroll
        for (int i = 0; i < 4; ++i) {
            float t0 = -3.0f, t1 = -3.0f;
            #pragma unroll
            for (int q = 0; q < 4; ++q) {
                t0 = fmaxf(t0, fmaxf(acc[i][q][0], acc[i][q][1]));
                t1 = fmaxf(t1, fmaxf(acc[i][q][2], acc[i][q][3]));
            }
            t0 = fmaxf(t0, __shfl_xor_sync(0xFFFFFFFFu, t0, 1));
            t0 = fmaxf(t0, __shfl_xor_sync(0xFFFFFFFFu, t0, 2));
            t1 = fmaxf(t1, __shfl_xor_sync(0xFFFFFFFFu, t1, 1));
            t1 = fmaxf(t1, __shfl_xor_sync(0xFFFFFFFFu, t1, 2));
            if ((l & 3) == 0) {
                int r0 = warp_m * 64 + i * 16 + (l >> 2);
                atomicMax(&s_max[r0], fmono(t0));
                atomicMax(&s_max[r0 + 8], fmono(t1));
            }
        }
        __syncthreads();
        if (tid < 128) {
            float v = funmono(s_max[tid]);
            g_smax[(size_t)(m0 + tid) * NSMAX + t] = v;
            runmax = fmaxf(runmax, v);
        }
        t = tn;
    }
    if (tid < 128) atomicMax(&g_gmaxU[m0 + tid], fmono(runmax));
}

// ---- 5 (S2): exact fp32 recheck + fused matched scatter --------------------
__global__ void k_exmat(const float* __restrict__ stm_V, const float* __restrict__ stm_e,
                        const float* __restrict__ stm_h,
                        float* __restrict__ oK, float* __restrict__ oV,
                        float* __restrict__ oe, float* __restrict__ oh) {
    int wid = threadIdx.x >> 5, lane = threadIdx.x & 31;
    int m = blockIdx.x * 8 + wid;
    int ns = g_scal[5];
    float thr = funmono(g_gmaxU[m]) - 0.01f;
    float4 kp4[16];
    const float4* kpr = reinterpret_cast<const float4*>(g_kpN + m * 64);
    #pragma unroll
    for (int i = 0; i < 16; ++i) kp4[i] = kpr[i];
    unsigned long long best = 0ull;
    for (int t = 0; t < ns; ++t) {
        if (g_smax[(size_t)m * NSMAX + t] < thr) continue;
        #pragma unroll
        for (int q = 0; q < 4; ++q) {
            int j = t * 128 + lane + q * 32;
            const float4* br = reinterpret_cast<const float4*>(g_lknC + (size_t)j * 64);
            float dot = 0.f;
            #pragma unroll
            for (int i = 0; i < 16; ++i) {
                float4 b4 = br[i];
                dot = fmaf(kp4[i].x, b4.x, dot);
                dot = fmaf(kp4[i].y, b4.y, dot);
                dot = fmaf(kp4[i].z, b4.z, dot);
                dot = fmaf(kp4[i].w, b4.w, dot);
            }
            unsigned long long pk =
                ((unsigned long long)fmono(dot) << 32) | g_ajinv[j];
            if (pk > best) best = pk;
        }
    }
    #pragma unroll
    for (int off = 16; off; off >>= 1) {
        unsigned long long o = __shfl_xor_sync(0xFFFFFFFFu, best, off);
        if (o > best) best = o;
    }
    float sim = funmono((unsigned)(best >> 32));
    int j = (int)(0xFFFFFFFFu - (unsigned)(best & 0xFFFFFFFFull));
    bool matched = (sim >= 0.5f);
    int s = g_sel[m];
    float om = g_omega[m];
    if (lane == 0) {
        g_unm[m] = matched ? 0 : 1;
        g_key[m] = stm_key(s, stm_h[s]);
        g_gmaxU[m] = 0u;
        if (matched) atomicAdd(&oh[j], om);
    }
    if (matched) {
        #pragma unroll
        for (int q = 0; q < 2; ++q) {
            int c = lane + q * 32;
            atomicAdd(&oK[(size_t)j * 64 + c], om * g_Kproj[m * 64 + c]);
        }
        #pragma unroll
        for (int q = 0; q < 4; ++q) {
            int c = lane + q * 32;
            atomicAdd(&oV[(size_t)j * 128 + c], om * stm_V[(size_t)s * 128 + c]);
        }
        if (lane < 4) atomicAdd(&oe[(size_t)j * 4 + lane], om * stm_e[(size_t)s * 4 + lane]);
    }
}

// ---- 6: rank unmatched (h desc, idx asc) -------------------------------------
__global__ void k_rank() {
    __shared__ unsigned long long sk[TOP_M];
    __shared__ unsigned char su[TOP_M];
    int t = threadIdx.x;
    for (int i = t; i < TOP_M; i += 256) { sk[i] = g_key[i]; su[i] = (unsigned char)g_unm[i]; }
    __syncthreads();
    int m = blockIdx.x * 256 + t;
    if (g_unm[m]) {
        unsigned long long k = sk[m];
        int r = 0;
        for (int i = 0; i < TOP_M; ++i) r += (su[i] && sk[i] > k);
        g_rank[m] = r;
    }
}

// ---- 7: unmatched fresh-slot writes (2048-way parallel) ----------------------
__global__ void k_unmatch(const float* __restrict__ stm_V, const float* __restrict__ stm_e,
                          float* __restrict__ oK, float* __restrict__ oV,
                          float* __restrict__ oe, float* __restrict__ oh) {
    int m = blockIdx.x;
    if (!g_unm[m]) return;
    int slot = g_free[g_rank[m]], c = threadIdx.x, s = g_sel[m];
    oK[(size_t)slot * 64 + c] = g_Kproj[m * 64 + c];
    oV[(size_t)slot * 128 + c] = stm_V[(size_t)s * 128 + c];
    oV[(size_t)slot * 128 + 64 + c] = stm_V[(size_t)s * 128 + 64 + c];
    if (c < 4) oe[(size_t)slot * 4 + c] = stm_e[(size_t)s * 4 + c];
    if (c == 0) oh[slot] = g_omega[m];
}

// ---- fused 3D gaussian blur + merge (branchless, div-free) -------------------
#define BLUR_SMEM ((10368 + 10368) * 4)   // 82944 B
__global__ void __launch_bounds__(256) k_blurAll(const float* __restrict__ stm_t,
                                                 const float* __restrict__ ltm_t,
                                                 float* __restrict__ oT) {
    extern __shared__ float p[];
    float* p0 = p;
    float* p0c = p + 576;
    float* p1 = p + 10368;
    float w[7], inv; gw(w, inv);
    int tid = threadIdx.x;
    int plane = blockIdx.x;
    int c = plane / 96, d = plane % 96;
    size_t cbase = (size_t)c * 96 * 9216;

    for (int i = tid; i < 576; i += 256) { p0[i] = 0.0f; p0[9792 + i] = 0.0f; }
    for (int i = tid; i < 1152; i += 256) {
        int row = i / 12, cc = i - row * 12;
        p1[row * 108 + (cc < 6 ? cc : 96 + cc)] = 0.0f;
    }

    float4 acc[9];
    #pragma unroll
    for (int e = 0; e < 9; ++e) acc[e] = make_float4(0.f, 0.f, 0.f, 0.f);
    #pragma unroll
    for (int t = -6; t <= 6; ++t) {
        int dd = d + t;
        if (dd < 0 || dd >= 96) continue;
        float ww = w[t < 0 ? -t : t];
        const float4* src = reinterpret_cast<const float4*>(stm_t + cbase + (size_t)dd * 9216);
        #pragma unroll
        for (int e = 0; e < 9; ++e) {
            float4 v = src[tid + e * 256];
            acc[e].x = fmaf(v.x, ww, acc[e].x);
            acc[e].y = fmaf(v.y, ww, acc[e].y);
            acc[e].z = fmaf(v.z, ww, acc[e].z);
            acc[e].w = fmaf(v.w, ww, acc[e].w);
        }
    }
    float4* d0 = reinterpret_cast<float4*>(p0c);
    #pragma unroll
    for (int e = 0; e < 9; ++e) {
        float4 v = acc[e];
        d0[tid + e * 256] = make_float4(v.x * inv, v.y * inv, v.z * inv, v.w * inv);
    }
    __syncthreads();

    {
        int h = tid / 96;
        int x = tid - h * 96;
        for (int i = tid; i < 9216; i += 256) {
            float a2 = p0c[i] * w[0];
            #pragma unroll
            for (int t = 1; t < 7; ++t)
                a2 += (p0c[i - t * 96] + p0c[i + t * 96]) * w[t];
            p1[h * 108 + 6 + x] = a2 * inv;
            x += 64; h += 2;
            if (x >= 96) { x -= 96; h += 1; }
        }
    }
    __syncthreads();

    {
        float xi = (c == 0) ? 0.005f : 0.003f;
        size_t base = cbase + (size_t)d * 9216;
        int h = tid / 96;
        int x = tid - h * 96;
        for (int i = tid; i < 9216; i += 256) {
            const float* row = p1 + h * 108 + 6 + x;
            float a2 = row[0] * w[0];
            #pragma unroll
            for (int t = 1; t < 7; ++t)
                a2 += (row[-t] + row[t]) * w[t];
            oT[base + i] = ltm_t[base + i] + xi * (a2 * inv);
            x += 64; h += 2;
            if (x >= 96) { x -= 96; h += 1; }
        }
    }
}

extern "C" void kernel_launch(void* const* d_in, const int* in_sizes, int n_in,
                              void* d_out, int out_size) {
    (void)in_sizes; (void)n_in; (void)out_size;
    const float* stm_K   = (const float*)d_in[0];
    const float* stm_V   = (const float*)d_in[1];
    const float* stm_e   = (const float*)d_in[2];
    const float* stm_h   = (const float*)d_in[3];
    const float* ltm_K   = (const float*)d_in[4];
    const float* ltm_V   = (const float*)d_in[5];
    const float* ltm_e   = (const float*)d_in[6];
    const float* ltm_h   = (const float*)d_in[7];
    const float* W       = (const float*)d_in[8];
    const float* b       = (const float*)d_in[9];
    const float* stm_t   = (const float*)d_in[10];
    const float* ltm_t   = (const float*)d_in[11];
    const float* fatigue = (const float*)d_in[12];
    const int*   stm_act = (const int*)d_in[13];
    const int*   ltm_act = (const int*)d_in[14];

    float* out = (float*)d_out;
    float* oK  = out;                 // 65536*64
    float* oV  = out + 4194304;       // 65536*128
    float* oe  = out + 12582912;      // 65536*4
    float* oh  = out + 12845056;      // 65536
    float* oSV = out + 12910592;      // 65536*128
    float* oT  = out + 21299200;      // 5*96^3
    float* oF  = out + 25722880;      // 1

    static cudaStream_t sB = 0, sD = 0;
    static cudaEvent_t eR = 0, eB = 0, eB2 = 0, eD = 0;
    static bool init_done = false;
    if (!init_done) {
        cudaFuncSetAttribute(k_blurAll, cudaFuncAttributeMaxDynamicSharedMemorySize, BLUR_SMEM);
        cudaStreamCreateWithFlags(&sB, cudaStreamNonBlocking);
        cudaStreamCreateWithFlags(&sD, cudaStreamNonBlocking);
        cudaEventCreateWithFlags(&eR, cudaEventDisableTiming);
        cudaEventCreateWithFlags(&eB, cudaEventDisableTiming);
        cudaEventCreateWithFlags(&eB2, cudaEventDisableTiming);
        cudaEventCreateWithFlags(&eD, cudaEventDisableTiming);
        init_done = true;
    }

    // fork
    cudaEventRecord(eR, 0);
    cudaStreamWaitEvent(sB, eR, 0);
    cudaStreamWaitEvent(sD, eR, 0);

    // enqueue order chosen so k_blurAll is launch #4 (ncu target this round)
    k_copy<<<3152, 256, 0, sB>>>((const float4*)ltm_K, (const float4*)ltm_V,
                                 (const float4*)ltm_e, (const float4*)ltm_h,
                                 (float4*)oK);
    cudaEventRecord(eB, sB);             // exmat depends on base copy only
    k_stmv<<<2048, 256, 0, sB>>>((const float4*)stm_V, (float4*)oSV);
    cudaEventRecord(eB2, sB);
    k_histlkn<<<4096, 256>>>((const float4*)ltm_K, ltm_act, stm_h, stm_act);  // #3
    k_blurAll<<<480, 256, BLUR_SMEM, sD>>>(stm_t, ltm_t, oT);                 // #4
    cudaEventRecord(eD, sD);

    // critical path
    k_prep<<<2, 1024>>>(fatigue, oF, ltm_act);
    k_compact<<<64, 1024>>>(stm_h, stm_act);
    k_proj<<<2048, 64>>>(stm_K, stm_h, W, b);
    k_simsT<<<dim3(16, 18), 256>>>();

    cudaStreamWaitEvent(0, eB, 0);
    k_exmat<<<256, 256>>>(stm_V, stm_e, stm_h, oK, oV, oe, oh);
    k_rank<<<8, 256>>>();
    k_unmatch<<<2048, 64>>>(stm_V, stm_e, oK, oV, oe, oh);

    // join side chains
    cudaStreamWaitEvent(0, eB2, 0);
    cudaStreamWaitEvent(0, eD, 0);
}